// round 1
// baseline (speedup 1.0000x reference)
#include <cuda_runtime.h>
#include <math.h>

#define DIM 768
#define HID 1536
#define BATCH 64
#define TOK 256
#define MROWS (BATCH*TOK)   /* 16384 */
#define LN_EPS 1e-6f

/* ------------------------------ scratch ------------------------------ */
__device__ float g_t [MROWS*DIM];   /* residual stream       48 MB */
__device__ float g_y [MROWS*DIM];   /* LN / FFT workspace    48 MB */
__device__ float g_h [MROWS*HID];   /* MLP hidden            96 MB */
__device__ float g_fr[BATCH*16*9*DIM]; /* spectrum real      28 MB */
__device__ float g_fi[BATCH*16*9*DIM]; /* spectrum imag      28 MB */

/* ------------------------------ im2col ------------------------------ */
__global__ __launch_bounds__(256) void im2col_k(const float* __restrict__ x,
                                                float* __restrict__ out) {
    int idx = blockIdx.x * 256 + threadIdx.x;       /* 16384*768 threads */
    int k = idx % DIM;
    int m = idx / DIM;
    int b = m >> 8;          int p  = m & 255;
    int hp = p >> 4;         int wp = p & 15;
    int c  = k >> 8;         int r  = k & 255;
    int ph = r >> 4;         int pw = r & 15;
    out[idx] = x[((size_t)(b*3 + c)*256 + hp*16 + ph)*256 + wp*16 + pw];
}

/* ------------------------------ GEMM: C = A[M,K] * B[N,K]^T ------------------------------ */
/* EPI: 0 = +bias[n] + pos[(m%256)*N+n]   1 = gelu(.+bias)   2 = C += . + bias (residual) */
template<int EPI>
__global__ __launch_bounds__(256) void gemm_tn(
    const float* __restrict__ A, const float* __restrict__ B,
    const float* __restrict__ bias, const float* __restrict__ extra,
    float* __restrict__ C, int M, int N, int K)
{
    __shared__ float As[16][128];
    __shared__ float Bs[16][64];
    const int tid = threadIdx.x;
    const int m0 = blockIdx.y * 128, n0 = blockIdx.x * 64;
    const int ty = tid >> 4, tx = tid & 15;
    float acc[8][4] = {};

    for (int k0 = 0; k0 < K; k0 += 16) {
        #pragma unroll
        for (int l = 0; l < 2; l++) {
            int f4  = tid + l * 256;
            int row = f4 >> 2, c4 = f4 & 3;
            float4 v = *(const float4*)(A + (size_t)(m0 + row) * K + k0 + c4 * 4);
            As[c4*4+0][row] = v.x; As[c4*4+1][row] = v.y;
            As[c4*4+2][row] = v.z; As[c4*4+3][row] = v.w;
        }
        {
            int row = tid >> 2, c4 = tid & 3;
            float4 v = *(const float4*)(B + (size_t)(n0 + row) * K + k0 + c4 * 4);
            Bs[c4*4+0][row] = v.x; Bs[c4*4+1][row] = v.y;
            Bs[c4*4+2][row] = v.z; Bs[c4*4+3][row] = v.w;
        }
        __syncthreads();
        #pragma unroll
        for (int kk = 0; kk < 16; kk++) {
            float4 a0 = *(const float4*)&As[kk][ty*8];
            float4 a1 = *(const float4*)&As[kk][ty*8+4];
            float4 b0 = *(const float4*)&Bs[kk][tx*4];
            float a[8] = {a0.x,a0.y,a0.z,a0.w,a1.x,a1.y,a1.z,a1.w};
            float bb[4] = {b0.x,b0.y,b0.z,b0.w};
            #pragma unroll
            for (int i = 0; i < 8; i++)
                #pragma unroll
                for (int j = 0; j < 4; j++)
                    acc[i][j] = fmaf(a[i], bb[j], acc[i][j]);
        }
        __syncthreads();
    }

    #pragma unroll
    for (int i = 0; i < 8; i++) {
        int m = m0 + ty*8 + i;
        #pragma unroll
        for (int j = 0; j < 4; j++) {
            int n = n0 + tx*4 + j;
            float v = acc[i][j] + bias[n];
            if (EPI == 0) v += extra[(size_t)(m & 255) * N + n];
            if (EPI == 1) v = 0.5f * v * (1.0f + erff(v * 0.70710678118654752f));
            size_t o = (size_t)m * N + n;
            if (EPI == 2) C[o] += v; else C[o] = v;
        }
    }
}

/* ------------------------------ reductions ------------------------------ */
__device__ __forceinline__ float2 block_reduce2(float s, float ss, float2* red) {
    int lane = threadIdx.x & 31, w = threadIdx.x >> 5;
    #pragma unroll
    for (int o = 16; o; o >>= 1) {
        s  += __shfl_down_sync(0xffffffffu, s,  o);
        ss += __shfl_down_sync(0xffffffffu, ss, o);
    }
    __syncthreads();                       /* safe for repeated calls */
    if (lane == 0) red[w] = make_float2(s, ss);
    __syncthreads();
    if (w == 0) {
        float2 v = (lane < 8) ? red[lane] : make_float2(0.f, 0.f);
        float a = v.x, bq = v.y;
        #pragma unroll
        for (int o = 4; o; o >>= 1) {
            a  += __shfl_down_sync(0xffffffffu, a,  o);
            bq += __shfl_down_sync(0xffffffffu, bq, o);
        }
        if (lane == 0) red[0] = make_float2(a, bq);
    }
    __syncthreads();
    return red[0];
}

/* LayerNorm over last dim (768): 1 block = 1 row */
__global__ __launch_bounds__(256) void ln_k(const float* __restrict__ in,
                                            float* __restrict__ out,
                                            const float* __restrict__ w,
                                            const float* __restrict__ b) {
    __shared__ float2 red[8];
    int row = blockIdx.x, t = threadIdx.x;
    const float* r = in + (size_t)row * DIM;
    float v0 = r[t], v1 = r[t+256], v2 = r[t+512];
    float2 R = block_reduce2(v0+v1+v2, v0*v0+v1*v1+v2*v2, red);
    float mean = R.x * (1.f/768.f);
    float var  = R.y * (1.f/768.f) - mean*mean;
    float rs = rsqrtf(var + LN_EPS);
    float* o = out + (size_t)row * DIM;
    o[t]     = (v0-mean)*rs*w[t]     + b[t];
    o[t+256] = (v1-mean)*rs*w[t+256] + b[t+256];
    o[t+512] = (v2-mean)*rs*w[t+512] + b[t+512];
}

/* ------------------------------ FFT stages ------------------------------ */
/* F1: rfft along w (16 -> 9).  thread = (b,h,d), coalesced over d */
__global__ __launch_bounds__(256) void fft_fwd_w(const float* __restrict__ y,
                                                 float* __restrict__ fr,
                                                 float* __restrict__ fi) {
    __shared__ float ct[16], st[16];
    int t = threadIdx.x;
    if (t < 16) { ct[t] = cospif(t * 0.125f); st[t] = sinpif(t * 0.125f); }
    __syncthreads();
    int gid = blockIdx.x * 256 + t;
    int d = gid % DIM; int hb = gid / DIM; int h = hb & 15; int b = hb >> 4;
    float v[16];
    const float* src = y + (size_t)(b*256 + h*16) * DIM + d;
    #pragma unroll
    for (int w = 0; w < 16; w++) v[w] = src[(size_t)w * DIM];
    size_t o = (size_t)(b*16 + h) * 9 * DIM + d;
    #pragma unroll
    for (int k = 0; k < 9; k++) {
        float sr = 0.f, si = 0.f;
        #pragma unroll
        for (int w = 0; w < 16; w++) {
            int m = (k * w) & 15;
            sr = fmaf(v[w],  ct[m], sr);
            si = fmaf(v[w], -st[m], si);
        }
        fr[o + (size_t)k * DIM] = sr;
        fi[o + (size_t)k * DIM] = si;
    }
}

/* F2: complex fft along h, modulate by filter, complex ifft along h. thread = (b,k,d) */
__global__ __launch_bounds__(256) void fft_h_mod(float* __restrict__ fr,
                                                 float* __restrict__ fi,
                                                 const float* __restrict__ cw) {
    __shared__ float ct[16], st[16];
    int t = threadIdx.x;
    if (t < 16) { ct[t] = cospif(t * 0.125f); st[t] = sinpif(t * 0.125f); }
    __syncthreads();
    int gid = blockIdx.x * 256 + t;       /* 64*9*768 */
    int d = gid % DIM; int kb = gid / DIM; int k = kb % 9; int b = kb / 9;
    size_t base = ((size_t)b * 16 * 9 + k) * DIM + d;   /* + h*9*DIM */
    float gr[16], gi[16];
    #pragma unroll
    for (int h = 0; h < 16; h++) {
        gr[h] = fr[base + (size_t)h * 9 * DIM];
        gi[h] = fi[base + (size_t)h * 9 * DIM];
    }
    float Gr[16], Gi[16];
    #pragma unroll
    for (int u = 0; u < 16; u++) {
        float ar = 0.f, ai = 0.f;
        #pragma unroll
        for (int h = 0; h < 16; h++) {
            int m = (u * h) & 15; float c = ct[m], s = st[m];
            ar = fmaf(gr[h], c, fmaf(gi[h],  s, ar));
            ai = fmaf(gi[h], c, fmaf(gr[h], -s, ai));
        }
        const float* wp = cw + ((size_t)(u*9 + k) * DIM + d) * 2;
        float wr = wp[0], wi = wp[1];
        Gr[u] = ar * wr - ai * wi;
        Gi[u] = ar * wi + ai * wr;
    }
    #pragma unroll
    for (int h = 0; h < 16; h++) {
        float ar = 0.f, ai = 0.f;
        #pragma unroll
        for (int u = 0; u < 16; u++) {
            int m = (u * h) & 15; float c = ct[m], s = st[m];
            ar = fmaf(Gr[u], c, fmaf(Gi[u], -s, ar));
            ai = fmaf(Gr[u], s, fmaf(Gi[u],  c, ai));
        }
        fr[base + (size_t)h * 9 * DIM] = ar;
        fi[base + (size_t)h * 9 * DIM] = ai;
    }
}

/* F3: irfft along w (9 -> 16), drops imag of DC & Nyquist, folds 1/256 ortho norm */
__global__ __launch_bounds__(256) void fft_inv_w(const float* __restrict__ fr,
                                                 const float* __restrict__ fi,
                                                 float* __restrict__ y) {
    __shared__ float ct[16], st[16];
    int t = threadIdx.x;
    if (t < 16) { ct[t] = cospif(t * 0.125f); st[t] = sinpif(t * 0.125f); }
    __syncthreads();
    int gid = blockIdx.x * 256 + t;
    int d = gid % DIM; int hb = gid / DIM; int h = hb & 15; int b = hb >> 4;
    size_t base = (size_t)(b*16 + h) * 9 * DIM + d;
    float vr[9], vi[9];
    #pragma unroll
    for (int k = 0; k < 9; k++) {
        vr[k] = fr[base + (size_t)k * DIM];
        vi[k] = fi[base + (size_t)k * DIM];
    }
    float* dst = y + (size_t)(b*256 + h*16) * DIM + d;
    #pragma unroll
    for (int w = 0; w < 16; w++) {
        float s = vr[0] + ((w & 1) ? -vr[8] : vr[8]);
        #pragma unroll
        for (int k = 1; k < 8; k++) {
            int m = (k * w) & 15;
            s = fmaf(2.f * vr[k], ct[m], s);
            s = fmaf(-2.f * vi[k], st[m], s);
        }
        dst[(size_t)w * DIM] = s * (1.f / 256.f);
    }
}

/* ------------------------------ final LN + mean + head ------------------------------ */
__global__ __launch_bounds__(256) void head_k(const float* __restrict__ tt,
                                              const float* __restrict__ nw,
                                              const float* __restrict__ nb,
                                              const float* __restrict__ hw,
                                              const float* __restrict__ hb,
                                              float* __restrict__ out) {
    __shared__ float2 red[8];
    int b = blockIdx.x, t = threadIdx.x;
    float a0 = 0.f, a1 = 0.f, a2 = 0.f;
    for (int p = 0; p < 256; p++) {
        const float* r = tt + (size_t)(b*256 + p) * DIM;
        float v0 = r[t], v1 = r[t+256], v2 = r[t+512];
        float2 R = block_reduce2(v0+v1+v2, v0*v0+v1*v1+v2*v2, red);
        float mean = R.x * (1.f/768.f);
        float var  = R.y * (1.f/768.f) - mean*mean;
        float rs = rsqrtf(var + LN_EPS);
        a0 += (v0-mean)*rs; a1 += (v1-mean)*rs; a2 += (v2-mean)*rs;
    }
    /* mean over tokens of (x_hat*w + b) = (sum x_hat)*w/256 + b */
    float f0 = a0 * nw[t]     * (1.f/256.f) + nb[t];
    float f1 = a1 * nw[t+256] * (1.f/256.f) + nb[t+256];
    float f2 = a2 * nw[t+512] * (1.f/256.f) + nb[t+512];
    float p0 = f0*hw[t]       + f1*hw[t+256]     + f2*hw[t+512];
    float p1 = f0*hw[768+t]   + f1*hw[768+t+256] + f2*hw[768+t+512];
    float2 R = block_reduce2(p0, p1, red);
    if (t == 0) {
        out[b*2 + 0] = R.x + hb[0];
        out[b*2 + 1] = R.y + hb[1];
    }
}

/* ------------------------------ launch ------------------------------ */
extern "C" void kernel_launch(void* const* d_in, const int* in_sizes, int n_in,
                              void* d_out, int out_size) {
    const float* x      = (const float*)d_in[0];
    const float* conv_w = (const float*)d_in[1];
    const float* conv_b = (const float*)d_in[2];
    const float* pos    = (const float*)d_in[3];
    const float* cw     = (const float*)d_in[4];
    const float* ln1w   = (const float*)d_in[5];
    const float* ln1b   = (const float*)d_in[6];
    const float* ln2w   = (const float*)d_in[7];
    const float* ln2b   = (const float*)d_in[8];
    const float* fc1w   = (const float*)d_in[9];
    const float* fc1b   = (const float*)d_in[10];
    const float* fc2w   = (const float*)d_in[11];
    const float* fc2b   = (const float*)d_in[12];
    const float* normw  = (const float*)d_in[13];
    const float* normb  = (const float*)d_in[14];
    const float* headw  = (const float*)d_in[15];
    const float* headb  = (const float*)d_in[16];
    float* out = (float*)d_out;
    (void)in_sizes; (void)n_in; (void)out_size;

    float *pt, *py, *ph, *pfr, *pfi;
    cudaGetSymbolAddress((void**)&pt,  g_t);
    cudaGetSymbolAddress((void**)&py,  g_y);
    cudaGetSymbolAddress((void**)&ph,  g_h);
    cudaGetSymbolAddress((void**)&pfr, g_fr);
    cudaGetSymbolAddress((void**)&pfi, g_fi);

    /* patch embed: im2col then GEMM(+bias+pos) */
    im2col_k<<<(MROWS * DIM) / 256, 256>>>(x, py);
    gemm_tn<0><<<dim3(DIM/64, MROWS/128), 256>>>(py, conv_w, conv_b, pos, pt,
                                                 MROWS, DIM, DIM);

    const int nF1 = (BATCH * 16 * DIM) / 256;   /* 3072 */
    const int nF2 = (BATCH * 9  * DIM) / 256;   /* 1728 */

    for (int i = 0; i < 8; i++) {
        ln_k<<<MROWS, 256>>>(pt, py, ln1w + i*DIM, ln1b + i*DIM);
        fft_fwd_w<<<nF1, 256>>>(py, pfr, pfi);
        fft_h_mod<<<nF2, 256>>>(pfr, pfi, cw + (size_t)i * 16 * 9 * DIM * 2);
        fft_inv_w<<<nF1, 256>>>(pfr, pfi, py);
        ln_k<<<MROWS, 256>>>(py, py, ln2w + i*DIM, ln2b + i*DIM);
        gemm_tn<1><<<dim3(HID/64, MROWS/128), 256>>>(py, fc1w + (size_t)i*HID*DIM,
                                                     fc1b + i*HID, nullptr, ph,
                                                     MROWS, HID, DIM);
        gemm_tn<2><<<dim3(DIM/64, MROWS/128), 256>>>(ph, fc2w + (size_t)i*DIM*HID,
                                                     fc2b + i*DIM, nullptr, pt,
                                                     MROWS, DIM, HID);
    }

    head_k<<<BATCH, 256>>>(pt, normw, normb, headw, headb, out);
}

// round 2
// speedup vs baseline: 2.3203x; 2.3203x over previous
#include <cuda_runtime.h>
#include <math.h>
#include <stdint.h>

#define DIM 768
#define HID 1536
#define BATCH 64
#define TOK 256
#define MROWS (BATCH*TOK)   /* 16384 */
#define LN_EPS 1e-6f

/* ------------------------------ scratch ------------------------------ */
__device__ float g_t [MROWS*DIM];      /* residual stream       48 MB */
__device__ float g_y [MROWS*DIM];      /* LN / FFT workspace    48 MB */
__device__ float g_h [MROWS*HID];      /* MLP hidden            96 MB */
__device__ float g_fr[BATCH*16*9*DIM]; /* spectrum real         28 MB */
__device__ float g_fi[BATCH*16*9*DIM]; /* spectrum imag         28 MB */

/* ------------------------------ im2col ------------------------------ */
__global__ __launch_bounds__(256) void im2col_k(const float* __restrict__ x,
                                                float* __restrict__ out) {
    int idx = blockIdx.x * 256 + threadIdx.x;
    int k = idx % DIM;
    int m = idx / DIM;
    int b = m >> 8;          int p  = m & 255;
    int hp = p >> 4;         int wp = p & 15;
    int c  = k >> 8;         int r  = k & 255;
    int ph = r >> 4;         int pw = r & 15;
    out[idx] = x[((size_t)(b*3 + c)*256 + hp*16 + ph)*256 + wp*16 + pw];
}

/* ------------------------------ tf32 tensor-core GEMM ------------------------------ */
/* C[M,N] = A[M,K] * B[N,K]^T, tf32 mma.sync, fp32 accumulate.
   CTA tile 128x128x32, 8 warps (4 along M x 2 along N), warp tile 32x64.
   EPI: 0 = +bias[n] + pos[(m%256)*N+n]   1 = gelu(.+bias)   2 = C += . + bias */

__device__ __forceinline__ uint32_t f2tf(float x) {
    uint32_t r;
    asm("cvt.rna.tf32.f32 %0, %1;" : "=r"(r) : "f"(x));
    return r;
}

__device__ __forceinline__ void mma_tf32(float* c, const uint32_t* a,
                                         uint32_t b0, uint32_t b1) {
    asm volatile(
        "mma.sync.aligned.m16n8k8.row.col.f32.tf32.tf32.f32 "
        "{%0,%1,%2,%3},{%4,%5,%6,%7},{%8,%9},{%0,%1,%2,%3};"
        : "+f"(c[0]), "+f"(c[1]), "+f"(c[2]), "+f"(c[3])
        : "r"(a[0]), "r"(a[1]), "r"(a[2]), "r"(a[3]), "r"(b0), "r"(b1));
}

#define TSTRIDE 36          /* 32 + 4 pad: frag-load banks = 4g+t, conflict-free */
#define TILEF (128*TSTRIDE) /* floats per tile buffer (4608) */
#define GEMM_SMEM (4*TILEF*4) /* 73728 bytes: A x2 stages + B x2 stages */

template<int EPI>
__global__ __launch_bounds__(256) void gemm_mma(
    const float* __restrict__ A, const float* __restrict__ B,
    const float* __restrict__ bias, const float* __restrict__ extra,
    float* __restrict__ C, int M, int N, int K)
{
    extern __shared__ float smem[];
    float* As = smem;            /* [2][TILEF] */
    float* Bs = smem + 2*TILEF;  /* [2][TILEF] */

    const int tid  = threadIdx.x;
    const int wid  = tid >> 5, lane = tid & 31;
    const int g    = lane >> 2, t = lane & 3;
    const int wm   = (wid & 3) * 32;
    const int wn   = (wid >> 2) * 64;
    const int m0   = blockIdx.y * 128, n0 = blockIdx.x * 128;

    float acc[2][8][4];
    #pragma unroll
    for (int i = 0; i < 2; i++)
        #pragma unroll
        for (int j = 0; j < 8; j++)
            #pragma unroll
            for (int q = 0; q < 4; q++) acc[i][j][q] = 0.f;

    const int nk = K >> 5;

    /* async tile loader: 128 rows x 32 cols, 16B chunks, fully coalesced */
    auto load_tiles = [&](int k0, int buf) {
        float* as = As + buf * TILEF;
        float* bs = Bs + buf * TILEF;
        #pragma unroll
        for (int l = 0; l < 4; l++) {
            int f = tid + l * 256;
            int row = f >> 3, c4 = f & 7;
            const float* gA = A + (size_t)(m0 + row) * K + k0 + c4 * 4;
            const float* gB = B + (size_t)(n0 + row) * K + k0 + c4 * 4;
            uint32_t sa = (uint32_t)__cvta_generic_to_shared(as + row * TSTRIDE + c4 * 4);
            uint32_t sb = (uint32_t)__cvta_generic_to_shared(bs + row * TSTRIDE + c4 * 4);
            asm volatile("cp.async.cg.shared.global [%0], [%1], 16;" :: "r"(sa), "l"(gA));
            asm volatile("cp.async.cg.shared.global [%0], [%1], 16;" :: "r"(sb), "l"(gB));
        }
    };

    load_tiles(0, 0);
    asm volatile("cp.async.commit_group;");

    for (int it = 0; it < nk; it++) {
        asm volatile("cp.async.wait_group 0;");
        __syncthreads();
        if (it + 1 < nk) {
            load_tiles((it + 1) << 5, (it + 1) & 1);
            asm volatile("cp.async.commit_group;");
        }
        const float* as = As + (it & 1) * TILEF;
        const float* bs = Bs + (it & 1) * TILEF;
        #pragma unroll
        for (int ks = 0; ks < 4; ks++) {
            const int k = ks * 8;
            uint32_t aF[2][4];
            #pragma unroll
            for (int mi = 0; mi < 2; mi++) {
                int r = wm + mi * 16 + g;
                aF[mi][0] = f2tf(as[(r    ) * TSTRIDE + k + t]);
                aF[mi][1] = f2tf(as[(r + 8) * TSTRIDE + k + t]);
                aF[mi][2] = f2tf(as[(r    ) * TSTRIDE + k + t + 4]);
                aF[mi][3] = f2tf(as[(r + 8) * TSTRIDE + k + t + 4]);
            }
            #pragma unroll
            for (int ni = 0; ni < 8; ni++) {
                int c = wn + ni * 8 + g;
                uint32_t b0 = f2tf(bs[c * TSTRIDE + k + t]);
                uint32_t b1 = f2tf(bs[c * TSTRIDE + k + t + 4]);
                mma_tf32(acc[0][ni], aF[0], b0, b1);
                mma_tf32(acc[1][ni], aF[1], b0, b1);
            }
        }
        __syncthreads();
    }

    /* epilogue */
    #pragma unroll
    for (int mi = 0; mi < 2; mi++) {
        #pragma unroll
        for (int ni = 0; ni < 8; ni++) {
            int row = m0 + wm + mi * 16 + g;
            int col = n0 + wn + ni * 8 + 2 * t;
            #pragma unroll
            for (int q = 0; q < 4; q++) {
                int m = row + (q >> 1) * 8;
                int n = col + (q & 1);
                float v = acc[mi][ni][q] + bias[n];
                if (EPI == 0) v += extra[(size_t)(m & 255) * N + n];
                if (EPI == 1) v = 0.5f * v * (1.0f + erff(v * 0.70710678118654752f));
                size_t o = (size_t)m * N + n;
                if (EPI == 2) C[o] += v; else C[o] = v;
            }
        }
    }
}

/* ------------------------------ reductions ------------------------------ */
__device__ __forceinline__ float2 block_reduce2(float s, float ss, float2* red) {
    int lane = threadIdx.x & 31, w = threadIdx.x >> 5;
    #pragma unroll
    for (int o = 16; o; o >>= 1) {
        s  += __shfl_down_sync(0xffffffffu, s,  o);
        ss += __shfl_down_sync(0xffffffffu, ss, o);
    }
    __syncthreads();
    if (lane == 0) red[w] = make_float2(s, ss);
    __syncthreads();
    if (w == 0) {
        float2 v = (lane < 8) ? red[lane] : make_float2(0.f, 0.f);
        float a = v.x, bq = v.y;
        #pragma unroll
        for (int o = 4; o; o >>= 1) {
            a  += __shfl_down_sync(0xffffffffu, a,  o);
            bq += __shfl_down_sync(0xffffffffu, bq, o);
        }
        if (lane == 0) red[0] = make_float2(a, bq);
    }
    __syncthreads();
    return red[0];
}

__global__ __launch_bounds__(256) void ln_k(const float* __restrict__ in,
                                            float* __restrict__ out,
                                            const float* __restrict__ w,
                                            const float* __restrict__ b) {
    __shared__ float2 red[8];
    int row = blockIdx.x, t = threadIdx.x;
    const float* r = in + (size_t)row * DIM;
    float v0 = r[t], v1 = r[t+256], v2 = r[t+512];
    float2 R = block_reduce2(v0+v1+v2, v0*v0+v1*v1+v2*v2, red);
    float mean = R.x * (1.f/768.f);
    float var  = R.y * (1.f/768.f) - mean*mean;
    float rs = rsqrtf(var + LN_EPS);
    float* o = out + (size_t)row * DIM;
    o[t]     = (v0-mean)*rs*w[t]     + b[t];
    o[t+256] = (v1-mean)*rs*w[t+256] + b[t+256];
    o[t+512] = (v2-mean)*rs*w[t+512] + b[t+512];
}

/* ------------------------------ FFT stages ------------------------------ */
__global__ __launch_bounds__(256) void fft_fwd_w(const float* __restrict__ y,
                                                 float* __restrict__ fr,
                                                 float* __restrict__ fi) {
    __shared__ float ct[16], st[16];
    int t = threadIdx.x;
    if (t < 16) { ct[t] = cospif(t * 0.125f); st[t] = sinpif(t * 0.125f); }
    __syncthreads();
    int gid = blockIdx.x * 256 + t;
    int d = gid % DIM; int hb = gid / DIM; int h = hb & 15; int b = hb >> 4;
    float v[16];
    const float* src = y + (size_t)(b*256 + h*16) * DIM + d;
    #pragma unroll
    for (int w = 0; w < 16; w++) v[w] = src[(size_t)w * DIM];
    size_t o = (size_t)(b*16 + h) * 9 * DIM + d;
    #pragma unroll
    for (int k = 0; k < 9; k++) {
        float sr = 0.f, si = 0.f;
        #pragma unroll
        for (int w = 0; w < 16; w++) {
            int m = (k * w) & 15;
            sr = fmaf(v[w],  ct[m], sr);
            si = fmaf(v[w], -st[m], si);
        }
        fr[o + (size_t)k * DIM] = sr;
        fi[o + (size_t)k * DIM] = si;
    }
}

__global__ __launch_bounds__(256) void fft_h_mod(float* __restrict__ fr,
                                                 float* __restrict__ fi,
                                                 const float* __restrict__ cw) {
    __shared__ float ct[16], st[16];
    int t = threadIdx.x;
    if (t < 16) { ct[t] = cospif(t * 0.125f); st[t] = sinpif(t * 0.125f); }
    __syncthreads();
    int gid = blockIdx.x * 256 + t;
    int d = gid % DIM; int kb = gid / DIM; int k = kb % 9; int b = kb / 9;
    size_t base = ((size_t)b * 16 * 9 + k) * DIM + d;
    float gr[16], gi[16];
    #pragma unroll
    for (int h = 0; h < 16; h++) {
        gr[h] = fr[base + (size_t)h * 9 * DIM];
        gi[h] = fi[base + (size_t)h * 9 * DIM];
    }
    float Gr[16], Gi[16];
    #pragma unroll
    for (int u = 0; u < 16; u++) {
        float ar = 0.f, ai = 0.f;
        #pragma unroll
        for (int h = 0; h < 16; h++) {
            int m = (u * h) & 15; float c = ct[m], s = st[m];
            ar = fmaf(gr[h], c, fmaf(gi[h],  s, ar));
            ai = fmaf(gi[h], c, fmaf(gr[h], -s, ai));
        }
        const float* wp = cw + ((size_t)(u*9 + k) * DIM + d) * 2;
        float wr = wp[0], wi = wp[1];
        Gr[u] = ar * wr - ai * wi;
        Gi[u] = ar * wi + ai * wr;
    }
    #pragma unroll
    for (int h = 0; h < 16; h++) {
        float ar = 0.f, ai = 0.f;
        #pragma unroll
        for (int u = 0; u < 16; u++) {
            int m = (u * h) & 15; float c = ct[m], s = st[m];
            ar = fmaf(Gr[u], c, fmaf(Gi[u], -s, ar));
            ai = fmaf(Gr[u], s, fmaf(Gi[u],  c, ai));
        }
        fr[base + (size_t)h * 9 * DIM] = ar;
        fi[base + (size_t)h * 9 * DIM] = ai;
    }
}

__global__ __launch_bounds__(256) void fft_inv_w(const float* __restrict__ fr,
                                                 const float* __restrict__ fi,
                                                 float* __restrict__ y) {
    __shared__ float ct[16], st[16];
    int t = threadIdx.x;
    if (t < 16) { ct[t] = cospif(t * 0.125f); st[t] = sinpif(t * 0.125f); }
    __syncthreads();
    int gid = blockIdx.x * 256 + t;
    int d = gid % DIM; int hb = gid / DIM; int h = hb & 15; int b = hb >> 4;
    size_t base = (size_t)(b*16 + h) * 9 * DIM + d;
    float vr[9], vi[9];
    #pragma unroll
    for (int k = 0; k < 9; k++) {
        vr[k] = fr[base + (size_t)k * DIM];
        vi[k] = fi[base + (size_t)k * DIM];
    }
    float* dst = y + (size_t)(b*256 + h*16) * DIM + d;
    #pragma unroll
    for (int w = 0; w < 16; w++) {
        float s = vr[0] + ((w & 1) ? -vr[8] : vr[8]);
        #pragma unroll
        for (int k = 1; k < 8; k++) {
            int m = (k * w) & 15;
            s = fmaf(2.f * vr[k], ct[m], s);
            s = fmaf(-2.f * vi[k], st[m], s);
        }
        dst[(size_t)w * DIM] = s * (1.f / 256.f);
    }
}

/* ------------------------------ final LN + mean + head ------------------------------ */
__global__ __launch_bounds__(256) void head_k(const float* __restrict__ tt,
                                              const float* __restrict__ nw,
                                              const float* __restrict__ nb,
                                              const float* __restrict__ hw,
                                              const float* __restrict__ hb,
                                              float* __restrict__ out) {
    __shared__ float2 red[8];
    int b = blockIdx.x, t = threadIdx.x;
    float a0 = 0.f, a1 = 0.f, a2 = 0.f;
    for (int p = 0; p < 256; p++) {
        const float* r = tt + (size_t)(b*256 + p) * DIM;
        float v0 = r[t], v1 = r[t+256], v2 = r[t+512];
        float2 R = block_reduce2(v0+v1+v2, v0*v0+v1*v1+v2*v2, red);
        float mean = R.x * (1.f/768.f);
        float var  = R.y * (1.f/768.f) - mean*mean;
        float rs = rsqrtf(var + LN_EPS);
        a0 += (v0-mean)*rs; a1 += (v1-mean)*rs; a2 += (v2-mean)*rs;
    }
    float f0 = a0 * nw[t]     * (1.f/256.f) + nb[t];
    float f1 = a1 * nw[t+256] * (1.f/256.f) + nb[t+256];
    float f2 = a2 * nw[t+512] * (1.f/256.f) + nb[t+512];
    float p0 = f0*hw[t]       + f1*hw[t+256]     + f2*hw[t+512];
    float p1 = f0*hw[768+t]   + f1*hw[768+t+256] + f2*hw[768+t+512];
    float2 R = block_reduce2(p0, p1, red);
    if (t == 0) {
        out[b*2 + 0] = R.x + hb[0];
        out[b*2 + 1] = R.y + hb[1];
    }
}

/* ------------------------------ launch ------------------------------ */
extern "C" void kernel_launch(void* const* d_in, const int* in_sizes, int n_in,
                              void* d_out, int out_size) {
    const float* x      = (const float*)d_in[0];
    const float* conv_w = (const float*)d_in[1];
    const float* conv_b = (const float*)d_in[2];
    const float* pos    = (const float*)d_in[3];
    const float* cw     = (const float*)d_in[4];
    const float* ln1w   = (const float*)d_in[5];
    const float* ln1b   = (const float*)d_in[6];
    const float* ln2w   = (const float*)d_in[7];
    const float* ln2b   = (const float*)d_in[8];
    const float* fc1w   = (const float*)d_in[9];
    const float* fc1b   = (const float*)d_in[10];
    const float* fc2w   = (const float*)d_in[11];
    const float* fc2b   = (const float*)d_in[12];
    const float* normw  = (const float*)d_in[13];
    const float* normb  = (const float*)d_in[14];
    const float* headw  = (const float*)d_in[15];
    const float* headb  = (const float*)d_in[16];
    float* out = (float*)d_out;
    (void)in_sizes; (void)n_in; (void)out_size;

    float *pt, *py, *ph, *pfr, *pfi;
    cudaGetSymbolAddress((void**)&pt,  g_t);
    cudaGetSymbolAddress((void**)&py,  g_y);
    cudaGetSymbolAddress((void**)&ph,  g_h);
    cudaGetSymbolAddress((void**)&pfr, g_fr);
    cudaGetSymbolAddress((void**)&pfi, g_fi);

    static bool attr_set = false;
    if (!attr_set) {
        cudaFuncSetAttribute(gemm_mma<0>, cudaFuncAttributeMaxDynamicSharedMemorySize, GEMM_SMEM);
        cudaFuncSetAttribute(gemm_mma<1>, cudaFuncAttributeMaxDynamicSharedMemorySize, GEMM_SMEM);
        cudaFuncSetAttribute(gemm_mma<2>, cudaFuncAttributeMaxDynamicSharedMemorySize, GEMM_SMEM);
        attr_set = true;
    }

    /* patch embed: im2col then tf32 GEMM(+bias+pos) */
    im2col_k<<<(MROWS * DIM) / 256, 256>>>(x, py);
    gemm_mma<0><<<dim3(DIM/128, MROWS/128), 256, GEMM_SMEM>>>(py, conv_w, conv_b, pos, pt,
                                                              MROWS, DIM, DIM);

    const int nF1 = (BATCH * 16 * DIM) / 256;
    const int nF2 = (BATCH * 9  * DIM) / 256;

    for (int i = 0; i < 8; i++) {
        ln_k<<<MROWS, 256>>>(pt, py, ln1w + i*DIM, ln1b + i*DIM);
        fft_fwd_w<<<nF1, 256>>>(py, pfr, pfi);
        fft_h_mod<<<nF2, 256>>>(pfr, pfi, cw + (size_t)i * 16 * 9 * DIM * 2);
        fft_inv_w<<<nF1, 256>>>(pfr, pfi, py);
        ln_k<<<MROWS, 256>>>(py, py, ln2w + i*DIM, ln2b + i*DIM);
        gemm_mma<1><<<dim3(HID/128, MROWS/128), 256, GEMM_SMEM>>>(
            py, fc1w + (size_t)i*HID*DIM, fc1b + i*HID, nullptr, ph, MROWS, HID, DIM);
        gemm_mma<2><<<dim3(DIM/128, MROWS/128), 256, GEMM_SMEM>>>(
            ph, fc2w + (size_t)i*DIM*HID, fc2b + i*DIM, nullptr, pt, MROWS, DIM, HID);
    }

    head_k<<<BATCH, 256>>>(pt, normw, normb, headw, headb, out);
}

// round 4
// speedup vs baseline: 2.4820x; 1.0697x over previous
#include <cuda_runtime.h>
#include <math.h>
#include <stdint.h>

#define DIM 768
#define HID 1536
#define BATCH 64
#define TOK 256
#define MROWS (BATCH*TOK)   /* 16384 */
#define LN_EPS 1e-6f

/* ------------------------------ scratch ------------------------------ */
__device__ float g_t [MROWS*DIM];      /* residual stream       48 MB */
__device__ float g_y [MROWS*DIM];      /* LN / FFT workspace    48 MB */
__device__ float g_h [MROWS*HID];      /* MLP hidden            96 MB */
__device__ float g_fr[BATCH*16*9*DIM]; /* spectrum real         28 MB */
__device__ float g_fi[BATCH*16*9*DIM]; /* spectrum imag         28 MB */
__device__ float g_w1[8*HID*DIM];      /* tf32-rounded fc1_w    38 MB */
__device__ float g_w2[8*DIM*HID];      /* tf32-rounded fc2_w    38 MB */
__device__ float g_wc[DIM*DIM];        /* tf32-rounded conv_w  2.3 MB */

/* ------------------------------ helpers ------------------------------ */
__device__ __forceinline__ float tf32r(float x) {
    uint32_t u;
    asm("cvt.rna.tf32.f32 %0, %1;" : "=r"(u) : "f"(x));
    return __uint_as_float(u);
}

__device__ __forceinline__ void mma_tf32(float* c, const uint32_t* a,
                                         uint32_t b0, uint32_t b1) {
    asm volatile(
        "mma.sync.aligned.m16n8k8.row.col.f32.tf32.tf32.f32 "
        "{%0,%1,%2,%3},{%4,%5,%6,%7},{%8,%9},{%0,%1,%2,%3};"
        : "+f"(c[0]), "+f"(c[1]), "+f"(c[2]), "+f"(c[3])
        : "r"(a[0]), "r"(a[1]), "r"(a[2]), "r"(a[3]), "r"(b0), "r"(b1));
}

/* ------------------------------ round weights ------------------------------ */
__global__ __launch_bounds__(256) void round_k(const float* __restrict__ s,
                                               float* __restrict__ d, int n) {
    int i = blockIdx.x * 256 + threadIdx.x;
    if (i < n) d[i] = tf32r(s[i]);
}

/* ------------------------------ im2col (tf32-rounded) ------------------------------ */
__global__ __launch_bounds__(256) void im2col_k(const float* __restrict__ x,
                                                float* __restrict__ out) {
    int idx = blockIdx.x * 256 + threadIdx.x;
    int k = idx % DIM;
    int m = idx / DIM;
    int b = m >> 8;          int p  = m & 255;
    int hp = p >> 4;         int wp = p & 15;
    int c  = k >> 8;         int r  = k & 255;
    int ph = r >> 4;         int pw = r & 15;
    out[idx] = tf32r(x[((size_t)(b*3 + c)*256 + hp*16 + ph)*256 + wp*16 + pw]);
}

/* ------------------------------ tf32 tensor-core GEMM ------------------------------ */
/* C[M,N] = A[M,K] * B[N,K]^T, all operands pre-rounded to tf32 in gmem.
   CTA tile 128x128x32, 8 warps (4 along M x 2 along N), warp tile 32x64.
   True double-buffer: one cp.async group per stage, wait_group 1.
   EPI: 0 = +bias[n] + pos[(m%256)*N+n]   1 = tf32(gelu(.+bias))   2 = C += . + bias */

#define TSTRIDE 36          /* 32 + 4 pad: frag-load banks = 4g+t, conflict-free */
#define TILEF (128*TSTRIDE) /* floats per tile buffer (4608) */
#define GEMM_SMEM (4*TILEF*4) /* 73728 bytes */

template<int EPI>
__global__ __launch_bounds__(256) void gemm_mma(
    const float* __restrict__ A, const float* __restrict__ B,
    const float* __restrict__ bias, const float* __restrict__ extra,
    float* __restrict__ C, int M, int N, int K)
{
    extern __shared__ float smem[];
    float* As = smem;            /* [2][TILEF] */
    float* Bs = smem + 2*TILEF;  /* [2][TILEF] */

    const int tid  = threadIdx.x;
    const int wid  = tid >> 5, lane = tid & 31;
    const int g    = lane >> 2, t = lane & 3;
    const int wm   = (wid & 3) * 32;
    const int wn   = (wid >> 2) * 64;
    const int m0   = blockIdx.y * 128, n0 = blockIdx.x * 128;

    float acc[2][8][4];
    #pragma unroll
    for (int i = 0; i < 2; i++)
        #pragma unroll
        for (int j = 0; j < 8; j++)
            #pragma unroll
            for (int q = 0; q < 4; q++) acc[i][j][q] = 0.f;

    const int nk = K >> 5;

    auto load_tiles = [&](int k0, int buf) {
        float* as = As + buf * TILEF;
        float* bs = Bs + buf * TILEF;
        #pragma unroll
        for (int l = 0; l < 4; l++) {
            int f = tid + l * 256;
            int row = f >> 3, c4 = f & 7;
            const float* gA = A + (size_t)(m0 + row) * K + k0 + c4 * 4;
            const float* gB = B + (size_t)(n0 + row) * K + k0 + c4 * 4;
            uint32_t sa = (uint32_t)__cvta_generic_to_shared(as + row * TSTRIDE + c4 * 4);
            uint32_t sb = (uint32_t)__cvta_generic_to_shared(bs + row * TSTRIDE + c4 * 4);
            asm volatile("cp.async.cg.shared.global [%0], [%1], 16;" :: "r"(sa), "l"(gA));
            asm volatile("cp.async.cg.shared.global [%0], [%1], 16;" :: "r"(sb), "l"(gB));
        }
        asm volatile("cp.async.commit_group;");
    };

    load_tiles(0, 0);

    for (int it = 0; it < nk; it++) {
        if (it + 1 < nk) {
            load_tiles((it + 1) << 5, (it + 1) & 1);
            asm volatile("cp.async.wait_group 1;");   /* current tile done, prefetch in flight */
        } else {
            asm volatile("cp.async.wait_group 0;");
        }
        __syncthreads();
        const uint32_t* as = (const uint32_t*)(As + (it & 1) * TILEF);
        const uint32_t* bs = (const uint32_t*)(Bs + (it & 1) * TILEF);
        #pragma unroll
        for (int ks = 0; ks < 4; ks++) {
            const int k = ks * 8;
            uint32_t aF[2][4];
            #pragma unroll
            for (int mi = 0; mi < 2; mi++) {
                int r = wm + mi * 16 + g;
                aF[mi][0] = as[(r    ) * TSTRIDE + k + t];
                aF[mi][1] = as[(r + 8) * TSTRIDE + k + t];
                aF[mi][2] = as[(r    ) * TSTRIDE + k + t + 4];
                aF[mi][3] = as[(r + 8) * TSTRIDE + k + t + 4];
            }
            #pragma unroll
            for (int ni = 0; ni < 8; ni++) {
                int c = wn + ni * 8 + g;
                uint32_t b0 = bs[c * TSTRIDE + k + t];
                uint32_t b1 = bs[c * TSTRIDE + k + t + 4];
                mma_tf32(acc[0][ni], aF[0], b0, b1);
                mma_tf32(acc[1][ni], aF[1], b0, b1);
            }
        }
        __syncthreads();
    }

    /* epilogue */
    #pragma unroll
    for (int mi = 0; mi < 2; mi++) {
        #pragma unroll
        for (int ni = 0; ni < 8; ni++) {
            int row = m0 + wm + mi * 16 + g;
            int col = n0 + wn + ni * 8 + 2 * t;
            #pragma unroll
            for (int q = 0; q < 4; q++) {
                int m = row + (q >> 1) * 8;
                int n = col + (q & 1);
                float v = acc[mi][ni][q] + bias[n];
                if (EPI == 0) v += extra[(size_t)(m & 255) * N + n];
                if (EPI == 1) {
                    v = 0.5f * v * (1.0f + erff(v * 0.70710678118654752f));
                    v = tf32r(v);
                }
                size_t o = (size_t)m * N + n;
                if (EPI == 2) C[o] += v; else C[o] = v;
            }
        }
    }
}

/* ------------------------------ reductions ------------------------------ */
__device__ __forceinline__ float2 block_reduce2(float s, float ss, float2* red) {
    int lane = threadIdx.x & 31, w = threadIdx.x >> 5;
    #pragma unroll
    for (int o = 16; o; o >>= 1) {
        s  += __shfl_down_sync(0xffffffffu, s,  o);
        ss += __shfl_down_sync(0xffffffffu, ss, o);
    }
    __syncthreads();
    if (lane == 0) red[w] = make_float2(s, ss);
    __syncthreads();
    if (w == 0) {
        float2 v = (lane < 8) ? red[lane] : make_float2(0.f, 0.f);
        float a = v.x, bq = v.y;
        #pragma unroll
        for (int o = 4; o; o >>= 1) {
            a  += __shfl_down_sync(0xffffffffu, a,  o);
            bq += __shfl_down_sync(0xffffffffu, bq, o);
        }
        if (lane == 0) red[0] = make_float2(a, bq);
    }
    __syncthreads();
    return red[0];
}

/* ROUND=1 -> tf32-round the output (feeds a GEMM A operand) */
template<int ROUND>
__global__ __launch_bounds__(256) void ln_k(const float* __restrict__ in,
                                            float* __restrict__ out,
                                            const float* __restrict__ w,
                                            const float* __restrict__ b) {
    __shared__ float2 red[8];
    int row = blockIdx.x, t = threadIdx.x;
    const float* r = in + (size_t)row * DIM;
    float v0 = r[t], v1 = r[t+256], v2 = r[t+512];
    float2 R = block_reduce2(v0+v1+v2, v0*v0+v1*v1+v2*v2, red);
    float mean = R.x * (1.f/768.f);
    float var  = R.y * (1.f/768.f) - mean*mean;
    float rs = rsqrtf(var + LN_EPS);
    float* o = out + (size_t)row * DIM;
    float o0 = (v0-mean)*rs*w[t]     + b[t];
    float o1 = (v1-mean)*rs*w[t+256] + b[t+256];
    float o2 = (v2-mean)*rs*w[t+512] + b[t+512];
    if (ROUND) { o0 = tf32r(o0); o1 = tf32r(o1); o2 = tf32r(o2); }
    o[t] = o0; o[t+256] = o1; o[t+512] = o2;
}

/* ------------------------------ FFT stages ------------------------------ */
__global__ __launch_bounds__(256) void fft_fwd_w(const float* __restrict__ y,
                                                 float* __restrict__ fr,
                                                 float* __restrict__ fi) {
    __shared__ float ct[16], st[16];
    int t = threadIdx.x;
    if (t < 16) { ct[t] = cospif(t * 0.125f); st[t] = sinpif(t * 0.125f); }
    __syncthreads();
    int gid = blockIdx.x * 256 + t;
    int d = gid % DIM; int hb = gid / DIM; int h = hb & 15; int b = hb >> 4;
    float v[16];
    const float* src = y + (size_t)(b*256 + h*16) * DIM + d;
    #pragma unroll
    for (int w = 0; w < 16; w++) v[w] = src[(size_t)w * DIM];
    size_t o = (size_t)(b*16 + h) * 9 * DIM + d;
    #pragma unroll
    for (int k = 0; k < 9; k++) {
        float sr = 0.f, si = 0.f;
        #pragma unroll
        for (int w = 0; w < 16; w++) {
            int m = (k * w) & 15;
            sr = fmaf(v[w],  ct[m], sr);
            si = fmaf(v[w], -st[m], si);
        }
        fr[o + (size_t)k * DIM] = sr;
        fi[o + (size_t)k * DIM] = si;
    }
}

__global__ __launch_bounds__(256) void fft_h_mod(float* __restrict__ fr,
                                                 float* __restrict__ fi,
                                                 const float* __restrict__ cw) {
    __shared__ float ct[16], st[16];
    int t = threadIdx.x;
    if (t < 16) { ct[t] = cospif(t * 0.125f); st[t] = sinpif(t * 0.125f); }
    __syncthreads();
    int gid = blockIdx.x * 256 + t;
    int d = gid % DIM; int kb = gid / DIM; int k = kb % 9; int b = kb / 9;
    size_t base = ((size_t)b * 16 * 9 + k) * DIM + d;
    float gr[16], gi[16];
    #pragma unroll
    for (int h = 0; h < 16; h++) {
        gr[h] = fr[base + (size_t)h * 9 * DIM];
        gi[h] = fi[base + (size_t)h * 9 * DIM];
    }
    float Gr[16], Gi[16];
    #pragma unroll
    for (int u = 0; u < 16; u++) {
        float ar = 0.f, ai = 0.f;
        #pragma unroll
        for (int h = 0; h < 16; h++) {
            int m = (u * h) & 15; float c = ct[m], s = st[m];
            ar = fmaf(gr[h], c, fmaf(gi[h],  s, ar));
            ai = fmaf(gi[h], c, fmaf(gr[h], -s, ai));
        }
        const float* wp = cw + ((size_t)(u*9 + k) * DIM + d) * 2;
        float wr = wp[0], wi = wp[1];
        Gr[u] = ar * wr - ai * wi;
        Gi[u] = ar * wi + ai * wr;
    }
    #pragma unroll
    for (int h = 0; h < 16; h++) {
        float ar = 0.f, ai = 0.f;
        #pragma unroll
        for (int u = 0; u < 16; u++) {
            int m = (u * h) & 15; float c = ct[m], s = st[m];
            ar = fmaf(Gr[u], c, fmaf(Gi[u], -s, ar));
            ai = fmaf(Gr[u], s, fmaf(Gi[u],  c, ai));
        }
        fr[base + (size_t)h * 9 * DIM] = ar;
        fi[base + (size_t)h * 9 * DIM] = ai;
    }
}

__global__ __launch_bounds__(256) void fft_inv_w(const float* __restrict__ fr,
                                                 const float* __restrict__ fi,
                                                 float* __restrict__ y) {
    __shared__ float ct[16], st[16];
    int t = threadIdx.x;
    if (t < 16) { ct[t] = cospif(t * 0.125f); st[t] = sinpif(t * 0.125f); }
    __syncthreads();
    int gid = blockIdx.x * 256 + t;
    int d = gid % DIM; int hb = gid / DIM; int h = hb & 15; int b = hb >> 4;
    size_t base = (size_t)(b*16 + h) * 9 * DIM + d;
    float vr[9], vi[9];
    #pragma unroll
    for (int k = 0; k < 9; k++) {
        vr[k] = fr[base + (size_t)k * DIM];
        vi[k] = fi[base + (size_t)k * DIM];
    }
    float* dst = y + (size_t)(b*256 + h*16) * DIM + d;
    #pragma unroll
    for (int w = 0; w < 16; w++) {
        float s = vr[0] + ((w & 1) ? -vr[8] : vr[8]);
        #pragma unroll
        for (int k = 1; k < 8; k++) {
            int m = (k * w) & 15;
            s = fmaf(2.f * vr[k], ct[m], s);
            s = fmaf(-2.f * vi[k], st[m], s);
        }
        dst[(size_t)w * DIM] = s * (1.f / 256.f);
    }
}

/* ------------------------------ final LN + mean + head ------------------------------ */
__global__ __launch_bounds__(256) void head_k(const float* __restrict__ tt,
                                              const float* __restrict__ nw,
                                              const float* __restrict__ nb,
                                              const float* __restrict__ hw,
                                              const float* __restrict__ hb,
                                              float* __restrict__ out) {
    __shared__ float2 red[8];
    int b = blockIdx.x, t = threadIdx.x;
    float a0 = 0.f, a1 = 0.f, a2 = 0.f;
    for (int p = 0; p < 256; p++) {
        const float* r = tt + (size_t)(b*256 + p) * DIM;
        float v0 = r[t], v1 = r[t+256], v2 = r[t+512];
        float2 R = block_reduce2(v0+v1+v2, v0*v0+v1*v1+v2*v2, red);
        float mean = R.x * (1.f/768.f);
        float var  = R.y * (1.f/768.f) - mean*mean;
        float rs = rsqrtf(var + LN_EPS);
        a0 += (v0-mean)*rs; a1 += (v1-mean)*rs; a2 += (v2-mean)*rs;
    }
    float f0 = a0 * nw[t]     * (1.f/256.f) + nb[t];
    float f1 = a1 * nw[t+256] * (1.f/256.f) + nb[t+256];
    float f2 = a2 * nw[t+512] * (1.f/256.f) + nb[t+512];
    float p0 = f0*hw[t]       + f1*hw[t+256]     + f2*hw[t+512];
    float p1 = f0*hw[768+t]   + f1*hw[768+t+256] + f2*hw[768+t+512];
    float2 R = block_reduce2(p0, p1, red);
    if (t == 0) {
        out[b*2 + 0] = R.x + hb[0];
        out[b*2 + 1] = R.y + hb[1];
    }
}

/* ------------------------------ launch ------------------------------ */
extern "C" void kernel_launch(void* const* d_in, const int* in_sizes, int n_in,
                              void* d_out, int out_size) {
    const float* x      = (const float*)d_in[0];
    const float* conv_w = (const float*)d_in[1];
    const float* conv_b = (const float*)d_in[2];
    const float* pos    = (const float*)d_in[3];
    const float* cw     = (const float*)d_in[4];
    const float* ln1w   = (const float*)d_in[5];
    const float* ln1b   = (const float*)d_in[6];
    const float* ln2w   = (const float*)d_in[7];
    const float* ln2b   = (const float*)d_in[8];
    const float* fc1w   = (const float*)d_in[9];
    const float* fc1b   = (const float*)d_in[10];
    const float* fc2w   = (const float*)d_in[11];
    const float* fc2b   = (const float*)d_in[12];
    const float* normw  = (const float*)d_in[13];
    const float* normb  = (const float*)d_in[14];
    const float* headw  = (const float*)d_in[15];
    const float* headb  = (const float*)d_in[16];
    float* out = (float*)d_out;
    (void)in_sizes; (void)n_in; (void)out_size;

    float *pt, *py, *ph, *pfr, *pfi, *pw1, *pw2, *pwc;
    cudaGetSymbolAddress((void**)&pt,  g_t);
    cudaGetSymbolAddress((void**)&py,  g_y);
    cudaGetSymbolAddress((void**)&ph,  g_h);
    cudaGetSymbolAddress((void**)&pfr, g_fr);
    cudaGetSymbolAddress((void**)&pfi, g_fi);
    cudaGetSymbolAddress((void**)&pw1, g_w1);
    cudaGetSymbolAddress((void**)&pw2, g_w2);
    cudaGetSymbolAddress((void**)&pwc, g_wc);

    static bool attr_set = false;
    if (!attr_set) {
        cudaFuncSetAttribute(gemm_mma<0>, cudaFuncAttributeMaxDynamicSharedMemorySize, GEMM_SMEM);
        cudaFuncSetAttribute(gemm_mma<1>, cudaFuncAttributeMaxDynamicSharedMemorySize, GEMM_SMEM);
        cudaFuncSetAttribute(gemm_mma<2>, cudaFuncAttributeMaxDynamicSharedMemorySize, GEMM_SMEM);
        attr_set = true;
    }

    /* tf32-round the weights into scratch */
    round_k<<<(DIM*DIM + 255)/256, 256>>>(conv_w, pwc, DIM*DIM);
    round_k<<<(8*HID*DIM + 255)/256, 256>>>(fc1w, pw1, 8*HID*DIM);
    round_k<<<(8*DIM*HID + 255)/256, 256>>>(fc2w, pw2, 8*DIM*HID);

    /* patch embed */
    im2col_k<<<(MROWS * DIM) / 256, 256>>>(x, py);
    gemm_mma<0><<<dim3(DIM/128, MROWS/128), 256, GEMM_SMEM>>>(py, pwc, conv_b, pos, pt,
                                                              MROWS, DIM, DIM);

    const int nF1 = (BATCH * 16 * DIM) / 256;
    const int nF2 = (BATCH * 9  * DIM) / 256;

    for (int i = 0; i < 8; i++) {
        ln_k<0><<<MROWS, 256>>>(pt, py, ln1w + i*DIM, ln1b + i*DIM);
        fft_fwd_w<<<nF1, 256>>>(py, pfr, pfi);
        fft_h_mod<<<nF2, 256>>>(pfr, pfi, cw + (size_t)i * 16 * 9 * DIM * 2);
        fft_inv_w<<<nF1, 256>>>(pfr, pfi, py);
        ln_k<1><<<MROWS, 256>>>(py, py, ln2w + i*DIM, ln2b + i*DIM);
        gemm_mma<1><<<dim3(HID/128, MROWS/128), 256, GEMM_SMEM>>>(
            py, pw1 + (size_t)i*HID*DIM, fc1b + i*HID, nullptr, ph, MROWS, HID, DIM);
        gemm_mma<2><<<dim3(DIM/128, MROWS/128), 256, GEMM_SMEM>>>(
            ph, pw2 + (size_t)i*DIM*HID, fc2b + i*DIM, nullptr, pt, MROWS, DIM, HID);
    }

    head_k<<<BATCH, 256>>>(pt, normw, normb, headw, headb, out);
}

// round 5
// speedup vs baseline: 4.3044x; 1.7343x over previous
#include <cuda_runtime.h>
#include <cuda_fp16.h>
#include <math.h>
#include <stdint.h>

#define DIM 768
#define HID 1536
#define BATCH 64
#define TOK 256
#define MROWS (BATCH*TOK)   /* 16384 */
#define LN_EPS 1e-6f

/* ------------------------------ scratch ------------------------------ */
__device__ float  g_t [MROWS*DIM];        /* residual stream fp32   48 MB */
__device__ float  g_y [MROWS*DIM];        /* FFT workspace fp32     48 MB */
__device__ float2 g_st[MROWS];            /* ln1 stats (mean,rstd)        */
__device__ float  g_fr[BATCH*16*9*DIM];   /* spectrum real          28 MB */
__device__ float  g_fi[BATCH*16*9*DIM];   /* spectrum imag          28 MB */
__device__ __half g_xh[MROWS*DIM];        /* im2col fp16            24 MB */
__device__ __half g_ah[MROWS*DIM];        /* ln2 out fp16           24 MB */
__device__ __half g_hh[MROWS*HID];        /* gelu hidden fp16       48 MB */
__device__ __half g_w1h[8*HID*DIM];       /* fc1_w fp16             19 MB */
__device__ __half g_w2h[8*DIM*HID];       /* fc2_w fp16             19 MB */
__device__ __half g_wch[DIM*DIM];         /* conv_w fp16           1.2 MB */

/* ------------------------------ helpers ------------------------------ */
__global__ __launch_bounds__(256) void round_h(const float* __restrict__ s,
                                               __half* __restrict__ d, int n) {
    int i = blockIdx.x * 256 + threadIdx.x;
    if (i < n) d[i] = __float2half(s[i]);
}

__global__ __launch_bounds__(256) void im2col_k(const float* __restrict__ x,
                                                __half* __restrict__ out) {
    int idx = blockIdx.x * 256 + threadIdx.x;
    int k = idx % DIM;
    int m = idx / DIM;
    int b = m >> 8;          int p  = m & 255;
    int hp = p >> 4;         int wp = p & 15;
    int c  = k >> 8;         int r  = k & 255;
    int ph = r >> 4;         int pw = r & 15;
    out[idx] = __float2half(x[((size_t)(b*3 + c)*256 + hp*16 + ph)*256 + wp*16 + pw]);
}

__device__ __forceinline__ void ldsm4(uint32_t& r0, uint32_t& r1,
                                      uint32_t& r2, uint32_t& r3, uint32_t addr) {
    asm volatile("ldmatrix.sync.aligned.m8n8.x4.shared.b16 {%0,%1,%2,%3}, [%4];"
                 : "=r"(r0), "=r"(r1), "=r"(r2), "=r"(r3) : "r"(addr));
}
__device__ __forceinline__ void mma_f16(float* c, uint32_t a0, uint32_t a1,
                                        uint32_t a2, uint32_t a3,
                                        uint32_t b0, uint32_t b1) {
    asm volatile(
        "mma.sync.aligned.m16n8k16.row.col.f32.f16.f16.f32 "
        "{%0,%1,%2,%3},{%4,%5,%6,%7},{%8,%9},{%0,%1,%2,%3};"
        : "+f"(c[0]), "+f"(c[1]), "+f"(c[2]), "+f"(c[3])
        : "r"(a0), "r"(a1), "r"(a2), "r"(a3), "r"(b0), "r"(b1));
}

/* ------------------------------ fp16 tensor-core GEMM ------------------------------ */
/* C[M,N] = A[M,K] * B[N,K]^T, fp16 in, fp32 acc.
   CTA 128x128x32, 8 warps (4 M x 2 N), warp tile 32x64.
   smem row = 32 halves @ 80B stride (conflict-free for ldmatrix + cp.async).
   EPI: 0 = fp32 +bias+pos   1 = fp16 gelu(.+bias)   2 = fp32 C += . + bias */

#define RSTR 40   /* halves per smem row (80 bytes) */

template<int EPI>
__global__ __launch_bounds__(256) void gemm_mma(
    const __half* __restrict__ A, const __half* __restrict__ B,
    const float* __restrict__ bias, const float* __restrict__ extra,
    void* __restrict__ Cv, int M, int N, int K)
{
    __shared__ __half As[2][128*RSTR];
    __shared__ __half Bs[2][128*RSTR];

    const int tid  = threadIdx.x;
    const int wid  = tid >> 5, lane = tid & 31;
    const int g    = lane >> 2, t = lane & 3;
    const int wm   = (wid & 3) * 32;
    const int wn   = (wid >> 2) * 64;
    const int m0   = blockIdx.y * 128, n0 = blockIdx.x * 128;

    float acc[2][8][4];
    #pragma unroll
    for (int i = 0; i < 2; i++)
        #pragma unroll
        for (int j = 0; j < 8; j++)
            #pragma unroll
            for (int q = 0; q < 4; q++) acc[i][j][q] = 0.f;

    const int nk = K >> 5;
    const int lrow = tid >> 2, lc = tid & 3;   /* loader: 64 rows per pass, 4 chunks */

    auto load_tiles = [&](int k0, int buf) {
        #pragma unroll
        for (int l = 0; l < 2; l++) {
            int row = lrow + l * 64;
            const __half* gA = A + (size_t)(m0 + row) * K + k0 + lc * 8;
            const __half* gB = B + (size_t)(n0 + row) * K + k0 + lc * 8;
            uint32_t sa = (uint32_t)__cvta_generic_to_shared(&As[buf][row * RSTR + lc * 8]);
            uint32_t sb = (uint32_t)__cvta_generic_to_shared(&Bs[buf][row * RSTR + lc * 8]);
            asm volatile("cp.async.cg.shared.global [%0], [%1], 16;" :: "r"(sa), "l"(gA));
            asm volatile("cp.async.cg.shared.global [%0], [%1], 16;" :: "r"(sb), "l"(gB));
        }
        asm volatile("cp.async.commit_group;");
    };

    /* lane-fixed ldmatrix address components */
    const int lq = lane >> 3, lr = lane & 7;
    const int a_row = (lq & 1) * 8 + lr;        /* + wm + mi*16 */
    const int a_chk = lq >> 1;                  /* + ks*2 */
    const int b_row = (lq >> 1) * 8 + lr;       /* + wn + ni2*16 */
    const int b_chk = lq & 1;                   /* + ks*2 */

    load_tiles(0, 0);

    for (int it = 0; it < nk; it++) {
        if (it + 1 < nk) {
            load_tiles((it + 1) << 5, (it + 1) & 1);
            asm volatile("cp.async.wait_group 1;");
        } else {
            asm volatile("cp.async.wait_group 0;");
        }
        __syncthreads();
        const __half* as = As[it & 1];
        const __half* bs = Bs[it & 1];
        #pragma unroll
        for (int ks = 0; ks < 2; ks++) {
            uint32_t aF[2][4];
            #pragma unroll
            for (int mi = 0; mi < 2; mi++) {
                uint32_t ad = (uint32_t)__cvta_generic_to_shared(
                    as + (wm + mi * 16 + a_row) * RSTR + (ks * 2 + a_chk) * 8);
                ldsm4(aF[mi][0], aF[mi][1], aF[mi][2], aF[mi][3], ad);
            }
            #pragma unroll
            for (int ni2 = 0; ni2 < 4; ni2++) {
                uint32_t b0, b1, b2, b3;
                uint32_t bd = (uint32_t)__cvta_generic_to_shared(
                    bs + (wn + ni2 * 16 + b_row) * RSTR + (ks * 2 + b_chk) * 8);
                ldsm4(b0, b1, b2, b3, bd);
                #pragma unroll
                for (int mi = 0; mi < 2; mi++) {
                    mma_f16(acc[mi][ni2*2],   aF[mi][0], aF[mi][1], aF[mi][2], aF[mi][3], b0, b1);
                    mma_f16(acc[mi][ni2*2+1], aF[mi][0], aF[mi][1], aF[mi][2], aF[mi][3], b2, b3);
                }
            }
        }
        __syncthreads();
    }

    /* epilogue */
    #pragma unroll
    for (int mi = 0; mi < 2; mi++) {
        #pragma unroll
        for (int ni = 0; ni < 8; ni++) {
            int row = m0 + wm + mi * 16 + g;
            int col = n0 + wn + ni * 8 + 2 * t;
            float bc0 = bias[col], bc1 = bias[col + 1];
            #pragma unroll
            for (int hf = 0; hf < 2; hf++) {
                int m = row + hf * 8;
                float v0 = acc[mi][ni][hf*2]   + bc0;
                float v1 = acc[mi][ni][hf*2+1] + bc1;
                size_t o = (size_t)m * N + col;
                if (EPI == 0) {
                    const float* e = extra + (size_t)(m & 255) * N + col;
                    v0 += e[0]; v1 += e[1];
                    *(float2*)((float*)Cv + o) = make_float2(v0, v1);
                } else if (EPI == 1) {
                    v0 = 0.5f * v0 * (1.0f + erff(v0 * 0.70710678118654752f));
                    v1 = 0.5f * v1 * (1.0f + erff(v1 * 0.70710678118654752f));
                    *(__half2*)((__half*)Cv + o) = __floats2half2_rn(v0, v1);
                } else {
                    float2 old = *(float2*)((float*)Cv + o);
                    *(float2*)((float*)Cv + o) = make_float2(old.x + v0, old.y + v1);
                }
            }
        }
    }
}

/* ------------------------------ reductions ------------------------------ */
__device__ __forceinline__ float2 block_reduce2(float s, float ss, float2* red) {
    int lane = threadIdx.x & 31, w = threadIdx.x >> 5;
    #pragma unroll
    for (int o = 16; o; o >>= 1) {
        s  += __shfl_down_sync(0xffffffffu, s,  o);
        ss += __shfl_down_sync(0xffffffffu, ss, o);
    }
    __syncthreads();
    if (lane == 0) red[w] = make_float2(s, ss);
    __syncthreads();
    if (w == 0) {
        float2 v = (lane < 8) ? red[lane] : make_float2(0.f, 0.f);
        float a = v.x, bq = v.y;
        #pragma unroll
        for (int o = 4; o; o >>= 1) {
            a  += __shfl_down_sync(0xffffffffu, a,  o);
            bq += __shfl_down_sync(0xffffffffu, bq, o);
        }
        if (lane == 0) red[0] = make_float2(a, bq);
    }
    __syncthreads();
    return red[0];
}

/* per-row LN stats of g_t: (mean, rstd) */
__global__ __launch_bounds__(256) void ln_stats_k(const float* __restrict__ in,
                                                  float2* __restrict__ st) {
    __shared__ float2 red[8];
    int row = blockIdx.x, t = threadIdx.x;
    const float* r = in + (size_t)row * DIM;
    float v0 = r[t], v1 = r[t+256], v2 = r[t+512];
    float2 R = block_reduce2(v0+v1+v2, v0*v0+v1*v1+v2*v2, red);
    if (t == 0) {
        float mean = R.x * (1.f/768.f);
        float var  = R.y * (1.f/768.f) - mean*mean;
        st[row] = make_float2(mean, rsqrtf(var + LN_EPS));
    }
}

/* LayerNorm -> fp16 out (feeds fc1) */
__global__ __launch_bounds__(256) void ln_to_h(const float* __restrict__ in,
                                               __half* __restrict__ out,
                                               const float* __restrict__ w,
                                               const float* __restrict__ b) {
    __shared__ float2 red[8];
    int row = blockIdx.x, t = threadIdx.x;
    const float* r = in + (size_t)row * DIM;
    float v0 = r[t], v1 = r[t+256], v2 = r[t+512];
    float2 R = block_reduce2(v0+v1+v2, v0*v0+v1*v1+v2*v2, red);
    float mean = R.x * (1.f/768.f);
    float var  = R.y * (1.f/768.f) - mean*mean;
    float rs = rsqrtf(var + LN_EPS);
    __half* o = out + (size_t)row * DIM;
    o[t]     = __float2half((v0-mean)*rs*w[t]     + b[t]);
    o[t+256] = __float2half((v1-mean)*rs*w[t+256] + b[t+256]);
    o[t+512] = __float2half((v2-mean)*rs*w[t+512] + b[t+512]);
}

/* ------------------------------ FFT stages ------------------------------ */
/* F1: ln1(applied inline via stats) + rfft along w (16 -> 9) */
__global__ __launch_bounds__(256) void fft_fwd_w(const float* __restrict__ tt,
                                                 const float2* __restrict__ st,
                                                 const float* __restrict__ lw,
                                                 const float* __restrict__ lb,
                                                 float* __restrict__ fr,
                                                 float* __restrict__ fi) {
    __shared__ float ct[16], stab[16];
    int t = threadIdx.x;
    if (t < 16) { ct[t] = cospif(t * 0.125f); stab[t] = sinpif(t * 0.125f); }
    __syncthreads();
    int gid = blockIdx.x * 256 + t;
    int d = gid % DIM; int hb = gid / DIM; int h = hb & 15; int b = hb >> 4;
    int rowbase = b*256 + h*16;
    float wd = lw[d], bd = lb[d];
    float v[16];
    const float* src = tt + (size_t)rowbase * DIM + d;
    #pragma unroll
    for (int w = 0; w < 16; w++) {
        float2 s = __ldg(&st[rowbase + w]);
        v[w] = (src[(size_t)w * DIM] - s.x) * s.y * wd + bd;
    }
    size_t o = (size_t)(b*16 + h) * 9 * DIM + d;
    #pragma unroll
    for (int k = 0; k < 9; k++) {
        float sr = 0.f, si = 0.f;
        #pragma unroll
        for (int w = 0; w < 16; w++) {
            int m = (k * w) & 15;
            sr = fmaf(v[w],  ct[m], sr);
            si = fmaf(v[w], -stab[m], si);
        }
        fr[o + (size_t)k * DIM] = sr;
        fi[o + (size_t)k * DIM] = si;
    }
}

__global__ __launch_bounds__(256) void fft_h_mod(float* __restrict__ fr,
                                                 float* __restrict__ fi,
                                                 const float* __restrict__ cw) {
    __shared__ float ct[16], st[16];
    int t = threadIdx.x;
    if (t < 16) { ct[t] = cospif(t * 0.125f); st[t] = sinpif(t * 0.125f); }
    __syncthreads();
    int gid = blockIdx.x * 256 + t;
    int d = gid % DIM; int kb = gid / DIM; int k = kb % 9; int b = kb / 9;
    size_t base = ((size_t)b * 16 * 9 + k) * DIM + d;
    float gr[16], gi[16];
    #pragma unroll
    for (int h = 0; h < 16; h++) {
        gr[h] = fr[base + (size_t)h * 9 * DIM];
        gi[h] = fi[base + (size_t)h * 9 * DIM];
    }
    float Gr[16], Gi[16];
    #pragma unroll
    for (int u = 0; u < 16; u++) {
        float ar = 0.f, ai = 0.f;
        #pragma unroll
        for (int h = 0; h < 16; h++) {
            int m = (u * h) & 15; float c = ct[m], s = st[m];
            ar = fmaf(gr[h], c, fmaf(gi[h],  s, ar));
            ai = fmaf(gi[h], c, fmaf(gr[h], -s, ai));
        }
        const float* wp = cw + ((size_t)(u*9 + k) * DIM + d) * 2;
        float wr = wp[0], wi = wp[1];
        Gr[u] = ar * wr - ai * wi;
        Gi[u] = ar * wi + ai * wr;
    }
    #pragma unroll
    for (int h = 0; h < 16; h++) {
        float ar = 0.f, ai = 0.f;
        #pragma unroll
        for (int u = 0; u < 16; u++) {
            int m = (u * h) & 15; float c = ct[m], s = st[m];
            ar = fmaf(Gr[u], c, fmaf(Gi[u], -s, ar));
            ai = fmaf(Gr[u], s, fmaf(Gi[u],  c, ai));
        }
        fr[base + (size_t)h * 9 * DIM] = ar;
        fi[base + (size_t)h * 9 * DIM] = ai;
    }
}

__global__ __launch_bounds__(256) void fft_inv_w(const float* __restrict__ fr,
                                                 const float* __restrict__ fi,
                                                 float* __restrict__ y) {
    __shared__ float ct[16], st[16];
    int t = threadIdx.x;
    if (t < 16) { ct[t] = cospif(t * 0.125f); st[t] = sinpif(t * 0.125f); }
    __syncthreads();
    int gid = blockIdx.x * 256 + t;
    int d = gid % DIM; int hb = gid / DIM; int h = hb & 15; int b = hb >> 4;
    size_t base = (size_t)(b*16 + h) * 9 * DIM + d;
    float vr[9], vi[9];
    #pragma unroll
    for (int k = 0; k < 9; k++) {
        vr[k] = fr[base + (size_t)k * DIM];
        vi[k] = fi[base + (size_t)k * DIM];
    }
    float* dst = y + (size_t)(b*256 + h*16) * DIM + d;
    #pragma unroll
    for (int w = 0; w < 16; w++) {
        float s = vr[0] + ((w & 1) ? -vr[8] : vr[8]);
        #pragma unroll
        for (int k = 1; k < 8; k++) {
            int m = (k * w) & 15;
            s = fmaf(2.f * vr[k], ct[m], s);
            s = fmaf(-2.f * vi[k], st[m], s);
        }
        dst[(size_t)w * DIM] = s * (1.f / 256.f);
    }
}

/* ------------------------------ final LN + mean + head ------------------------------ */
__global__ __launch_bounds__(256) void head_k(const float* __restrict__ tt,
                                              const float* __restrict__ nw,
                                              const float* __restrict__ nb,
                                              const float* __restrict__ hw,
                                              const float* __restrict__ hb,
                                              float* __restrict__ out) {
    __shared__ float2 red[8];
    int b = blockIdx.x, t = threadIdx.x;
    float a0 = 0.f, a1 = 0.f, a2 = 0.f;
    for (int p = 0; p < 256; p++) {
        const float* r = tt + (size_t)(b*256 + p) * DIM;
        float v0 = r[t], v1 = r[t+256], v2 = r[t+512];
        float2 R = block_reduce2(v0+v1+v2, v0*v0+v1*v1+v2*v2, red);
        float mean = R.x * (1.f/768.f);
        float var  = R.y * (1.f/768.f) - mean*mean;
        float rs = rsqrtf(var + LN_EPS);
        a0 += (v0-mean)*rs; a1 += (v1-mean)*rs; a2 += (v2-mean)*rs;
    }
    float f0 = a0 * nw[t]     * (1.f/256.f) + nb[t];
    float f1 = a1 * nw[t+256] * (1.f/256.f) + nb[t+256];
    float f2 = a2 * nw[t+512] * (1.f/256.f) + nb[t+512];
    float p0 = f0*hw[t]       + f1*hw[t+256]     + f2*hw[t+512];
    float p1 = f0*hw[768+t]   + f1*hw[768+t+256] + f2*hw[768+t+512];
    float2 R = block_reduce2(p0, p1, red);
    if (t == 0) {
        out[b*2 + 0] = R.x + hb[0];
        out[b*2 + 1] = R.y + hb[1];
    }
}

/* ------------------------------ launch ------------------------------ */
extern "C" void kernel_launch(void* const* d_in, const int* in_sizes, int n_in,
                              void* d_out, int out_size) {
    const float* x      = (const float*)d_in[0];
    const float* conv_w = (const float*)d_in[1];
    const float* conv_b = (const float*)d_in[2];
    const float* pos    = (const float*)d_in[3];
    const float* cw     = (const float*)d_in[4];
    const float* ln1w   = (const float*)d_in[5];
    const float* ln1b   = (const float*)d_in[6];
    const float* ln2w   = (const float*)d_in[7];
    const float* ln2b   = (const float*)d_in[8];
    const float* fc1w   = (const float*)d_in[9];
    const float* fc1b   = (const float*)d_in[10];
    const float* fc2w   = (const float*)d_in[11];
    const float* fc2b   = (const float*)d_in[12];
    const float* normw  = (const float*)d_in[13];
    const float* normb  = (const float*)d_in[14];
    const float* headw  = (const float*)d_in[15];
    const float* headb  = (const float*)d_in[16];
    float* out = (float*)d_out;
    (void)in_sizes; (void)n_in; (void)out_size;

    float *pt, *py, *pfr, *pfi;
    float2* pst;
    __half *pxh, *pah, *phh, *pw1h, *pw2h, *pwch;
    cudaGetSymbolAddress((void**)&pt,   g_t);
    cudaGetSymbolAddress((void**)&py,   g_y);
    cudaGetSymbolAddress((void**)&pst,  g_st);
    cudaGetSymbolAddress((void**)&pfr,  g_fr);
    cudaGetSymbolAddress((void**)&pfi,  g_fi);
    cudaGetSymbolAddress((void**)&pxh,  g_xh);
    cudaGetSymbolAddress((void**)&pah,  g_ah);
    cudaGetSymbolAddress((void**)&phh,  g_hh);
    cudaGetSymbolAddress((void**)&pw1h, g_w1h);
    cudaGetSymbolAddress((void**)&pw2h, g_w2h);
    cudaGetSymbolAddress((void**)&pwch, g_wch);

    /* fp16 weights */
    round_h<<<(DIM*DIM + 255)/256, 256>>>(conv_w, pwch, DIM*DIM);
    round_h<<<(8*HID*DIM + 255)/256, 256>>>(fc1w, pw1h, 8*HID*DIM);
    round_h<<<(8*DIM*HID + 255)/256, 256>>>(fc2w, pw2h, 8*DIM*HID);

    /* patch embed */
    im2col_k<<<(MROWS * DIM) / 256, 256>>>(x, pxh);
    gemm_mma<0><<<dim3(DIM/128, MROWS/128), 256>>>(pxh, pwch, conv_b, pos, pt,
                                                   MROWS, DIM, DIM);

    const int nF1 = (BATCH * 16 * DIM) / 256;
    const int nF2 = (BATCH * 9  * DIM) / 256;

    for (int i = 0; i < 8; i++) {
        ln_stats_k<<<MROWS, 256>>>(pt, pst);
        fft_fwd_w<<<nF1, 256>>>(pt, pst, ln1w + i*DIM, ln1b + i*DIM, pfr, pfi);
        fft_h_mod<<<nF2, 256>>>(pfr, pfi, cw + (size_t)i * 16 * 9 * DIM * 2);
        fft_inv_w<<<nF1, 256>>>(pfr, pfi, py);
        ln_to_h<<<MROWS, 256>>>(py, pah, ln2w + i*DIM, ln2b + i*DIM);
        gemm_mma<1><<<dim3(HID/128, MROWS/128), 256>>>(
            pah, pw1h + (size_t)i*HID*DIM, fc1b + i*HID, nullptr, phh, MROWS, HID, DIM);
        gemm_mma<2><<<dim3(DIM/128, MROWS/128), 256>>>(
            phh, pw2h + (size_t)i*DIM*HID, fc2b + i*DIM, nullptr, pt, MROWS, DIM, HID);
    }

    head_k<<<BATCH, 256>>>(pt, normw, normb, headw, headb, out);
}

// round 6
// speedup vs baseline: 4.4398x; 1.0315x over previous
#include <cuda_runtime.h>
#include <cuda_fp16.h>
#include <math.h>
#include <stdint.h>

#define DIM 768
#define HID 1536
#define BATCH 64
#define TOK 256
#define MROWS (BATCH*TOK)   /* 16384 */
#define LN_EPS 1e-6f

/* ------------------------------ scratch ------------------------------ */
__device__ float  g_t [MROWS*DIM];        /* residual stream fp32   48 MB */
__device__ float  g_y [MROWS*DIM];        /* FFT workspace fp32     48 MB */
__device__ float2 g_st[MROWS];            /* ln1 stats (mean,rstd)        */
__device__ float  g_fr[BATCH*16*9*DIM];   /* spectrum real          28 MB */
__device__ float  g_fi[BATCH*16*9*DIM];   /* spectrum imag          28 MB */
__device__ __half g_xh[MROWS*DIM];        /* im2col fp16            24 MB */
__device__ __half g_ah[MROWS*DIM];        /* ln2 out fp16           24 MB */
__device__ __half g_hh[MROWS*HID];        /* gelu hidden fp16       48 MB */
__device__ __half g_w1h[8*HID*DIM];       /* fc1_w fp16             19 MB */
__device__ __half g_w2h[8*DIM*HID];       /* fc2_w fp16             19 MB */
__device__ __half g_wch[DIM*DIM];         /* conv_w fp16           1.2 MB */

/* ------------------------------ helpers ------------------------------ */
__global__ __launch_bounds__(256) void round_h(const float* __restrict__ s,
                                               __half* __restrict__ d, int n) {
    int i = blockIdx.x * 256 + threadIdx.x;
    if (i < n) d[i] = __float2half(s[i]);
}

__global__ __launch_bounds__(256) void im2col_k(const float* __restrict__ x,
                                                __half* __restrict__ out) {
    int idx = blockIdx.x * 256 + threadIdx.x;
    int k = idx % DIM;
    int m = idx / DIM;
    int b = m >> 8;          int p  = m & 255;
    int hp = p >> 4;         int wp = p & 15;
    int c  = k >> 8;         int r  = k & 255;
    int ph = r >> 4;         int pw = r & 15;
    out[idx] = __float2half(x[((size_t)(b*3 + c)*256 + hp*16 + ph)*256 + wp*16 + pw]);
}

__device__ __forceinline__ void ldsm4(uint32_t& r0, uint32_t& r1,
                                      uint32_t& r2, uint32_t& r3, uint32_t addr) {
    asm volatile("ldmatrix.sync.aligned.m8n8.x4.shared.b16 {%0,%1,%2,%3}, [%4];"
                 : "=r"(r0), "=r"(r1), "=r"(r2), "=r"(r3) : "r"(addr));
}
__device__ __forceinline__ void mma_f16(float* c, uint32_t a0, uint32_t a1,
                                        uint32_t a2, uint32_t a3,
                                        uint32_t b0, uint32_t b1) {
    asm volatile(
        "mma.sync.aligned.m16n8k16.row.col.f32.f16.f16.f32 "
        "{%0,%1,%2,%3},{%4,%5,%6,%7},{%8,%9},{%0,%1,%2,%3};"
        : "+f"(c[0]), "+f"(c[1]), "+f"(c[2]), "+f"(c[3])
        : "r"(a0), "r"(a1), "r"(a2), "r"(a3), "r"(b0), "r"(b1));
}

/* ------------------------------ fp16 tensor-core GEMM ------------------------------ */
/* C[M,N] = A[M,K] * B[N,K]^T, fp16 in, fp32 acc.
   CTA 128x128x32, 8 warps (4 M x 2 N), warp tile 32x64.
   3-stage cp.async circular pipeline, ONE __syncthreads per k-chunk,
   prefetch distance 2.  smem rows @80B stride (conflict-free ldmatrix).
   EPI: 0 = fp32 +bias+pos   1 = fp16 gelu(.+bias)   2 = fp32 C += . + bias */

#define RSTR 40                 /* halves per smem row (80 bytes) */
#define STGH (128*RSTR)         /* halves per operand per stage   */
#define GSMEM (3*2*STGH*2)      /* 61440 bytes                    */

template<int EPI>
__global__ __launch_bounds__(256) void gemm_mma(
    const __half* __restrict__ A, const __half* __restrict__ B,
    const float* __restrict__ bias, const float* __restrict__ extra,
    void* __restrict__ Cv, int M, int N, int K)
{
    extern __shared__ __half sm[];   /* [3][A:STGH | B:STGH] */

    const int tid  = threadIdx.x;
    const int wid  = tid >> 5, lane = tid & 31;
    const int g    = lane >> 2, t = lane & 3;
    const int wm   = (wid & 3) * 32;
    const int wn   = (wid >> 2) * 64;
    const int m0   = blockIdx.y * 128, n0 = blockIdx.x * 128;

    float acc[2][8][4];
    #pragma unroll
    for (int i = 0; i < 2; i++)
        #pragma unroll
        for (int j = 0; j < 8; j++)
            #pragma unroll
            for (int q = 0; q < 4; q++) acc[i][j][q] = 0.f;

    const int nk = K >> 5;
    const int lrow = tid >> 2, lc = tid & 3;

    auto load_tiles = [&](int k0, int s) {
        __half* as = sm + s * 2 * STGH;
        __half* bs = as + STGH;
        #pragma unroll
        for (int l = 0; l < 2; l++) {
            int row = lrow + l * 64;
            const __half* gA = A + (size_t)(m0 + row) * K + k0 + lc * 8;
            const __half* gB = B + (size_t)(n0 + row) * K + k0 + lc * 8;
            uint32_t sa = (uint32_t)__cvta_generic_to_shared(as + row * RSTR + lc * 8);
            uint32_t sb = (uint32_t)__cvta_generic_to_shared(bs + row * RSTR + lc * 8);
            asm volatile("cp.async.cg.shared.global [%0], [%1], 16;" :: "r"(sa), "l"(gA));
            asm volatile("cp.async.cg.shared.global [%0], [%1], 16;" :: "r"(sb), "l"(gB));
        }
        asm volatile("cp.async.commit_group;");
    };

    /* lane-fixed ldmatrix address components */
    const int lq = lane >> 3, lr = lane & 7;
    const int a_row = (lq & 1) * 8 + lr;
    const int a_chk = lq >> 1;
    const int b_row = (lq >> 1) * 8 + lr;
    const int b_chk = lq & 1;

    load_tiles(0, 0);
    if (nk > 1) load_tiles(32, 1);

    int cur = 0, pre = 2;   /* compute stage, prefetch stage (it+2)%3 */
    for (int it = 0; it < nk; it++) {
        if (it == nk - 1) { asm volatile("cp.async.wait_group 0;"); }
        else              { asm volatile("cp.async.wait_group 1;"); }
        __syncthreads();
        if (it + 2 < nk) load_tiles((it + 2) << 5, pre);

        const __half* as = sm + cur * 2 * STGH;
        const __half* bs = as + STGH;
        #pragma unroll
        for (int ks = 0; ks < 2; ks++) {
            uint32_t aF[2][4];
            #pragma unroll
            for (int mi = 0; mi < 2; mi++) {
                uint32_t ad = (uint32_t)__cvta_generic_to_shared(
                    as + (wm + mi * 16 + a_row) * RSTR + (ks * 2 + a_chk) * 8);
                ldsm4(aF[mi][0], aF[mi][1], aF[mi][2], aF[mi][3], ad);
            }
            #pragma unroll
            for (int ni2 = 0; ni2 < 4; ni2++) {
                uint32_t b0, b1, b2, b3;
                uint32_t bd = (uint32_t)__cvta_generic_to_shared(
                    bs + (wn + ni2 * 16 + b_row) * RSTR + (ks * 2 + b_chk) * 8);
                ldsm4(b0, b1, b2, b3, bd);
                #pragma unroll
                for (int mi = 0; mi < 2; mi++) {
                    mma_f16(acc[mi][ni2*2],   aF[mi][0], aF[mi][1], aF[mi][2], aF[mi][3], b0, b1);
                    mma_f16(acc[mi][ni2*2+1], aF[mi][0], aF[mi][1], aF[mi][2], aF[mi][3], b2, b3);
                }
            }
        }
        cur = (cur == 2) ? 0 : cur + 1;
        pre = (pre == 2) ? 0 : pre + 1;
    }

    /* epilogue */
    #pragma unroll
    for (int mi = 0; mi < 2; mi++) {
        #pragma unroll
        for (int ni = 0; ni < 8; ni++) {
            int row = m0 + wm + mi * 16 + g;
            int col = n0 + wn + ni * 8 + 2 * t;
            float bc0 = bias[col], bc1 = bias[col + 1];
            #pragma unroll
            for (int hf = 0; hf < 2; hf++) {
                int m = row + hf * 8;
                float v0 = acc[mi][ni][hf*2]   + bc0;
                float v1 = acc[mi][ni][hf*2+1] + bc1;
                size_t o = (size_t)m * N + col;
                if (EPI == 0) {
                    const float* e = extra + (size_t)(m & 255) * N + col;
                    v0 += e[0]; v1 += e[1];
                    *(float2*)((float*)Cv + o) = make_float2(v0, v1);
                } else if (EPI == 1) {
                    v0 = 0.5f * v0 * (1.0f + erff(v0 * 0.70710678118654752f));
                    v1 = 0.5f * v1 * (1.0f + erff(v1 * 0.70710678118654752f));
                    *(__half2*)((__half*)Cv + o) = __floats2half2_rn(v0, v1);
                } else {
                    float2 old = *(float2*)((float*)Cv + o);
                    *(float2*)((float*)Cv + o) = make_float2(old.x + v0, old.y + v1);
                }
            }
        }
    }
}

/* ------------------------------ reductions ------------------------------ */
__device__ __forceinline__ float2 block_reduce2(float s, float ss, float2* red) {
    int lane = threadIdx.x & 31, w = threadIdx.x >> 5;
    #pragma unroll
    for (int o = 16; o; o >>= 1) {
        s  += __shfl_down_sync(0xffffffffu, s,  o);
        ss += __shfl_down_sync(0xffffffffu, ss, o);
    }
    __syncthreads();
    if (lane == 0) red[w] = make_float2(s, ss);
    __syncthreads();
    if (w == 0) {
        float2 v = (lane < 8) ? red[lane] : make_float2(0.f, 0.f);
        float a = v.x, bq = v.y;
        #pragma unroll
        for (int o = 4; o; o >>= 1) {
            a  += __shfl_down_sync(0xffffffffu, a,  o);
            bq += __shfl_down_sync(0xffffffffu, bq, o);
        }
        if (lane == 0) red[0] = make_float2(a, bq);
    }
    __syncthreads();
    return red[0];
}

/* per-row LN stats of g_t: (mean, rstd) */
__global__ __launch_bounds__(256) void ln_stats_k(const float* __restrict__ in,
                                                  float2* __restrict__ st) {
    __shared__ float2 red[8];
    int row = blockIdx.x, t = threadIdx.x;
    const float* r = in + (size_t)row * DIM;
    float v0 = r[t], v1 = r[t+256], v2 = r[t+512];
    float2 R = block_reduce2(v0+v1+v2, v0*v0+v1*v1+v2*v2, red);
    if (t == 0) {
        float mean = R.x * (1.f/768.f);
        float var  = R.y * (1.f/768.f) - mean*mean;
        st[row] = make_float2(mean, rsqrtf(var + LN_EPS));
    }
}

/* LayerNorm -> fp16 out (feeds fc1) */
__global__ __launch_bounds__(256) void ln_to_h(const float* __restrict__ in,
                                               __half* __restrict__ out,
                                               const float* __restrict__ w,
                                               const float* __restrict__ b) {
    __shared__ float2 red[8];
    int row = blockIdx.x, t = threadIdx.x;
    const float* r = in + (size_t)row * DIM;
    float v0 = r[t], v1 = r[t+256], v2 = r[t+512];
    float2 R = block_reduce2(v0+v1+v2, v0*v0+v1*v1+v2*v2, red);
    float mean = R.x * (1.f/768.f);
    float var  = R.y * (1.f/768.f) - mean*mean;
    float rs = rsqrtf(var + LN_EPS);
    __half* o = out + (size_t)row * DIM;
    o[t]     = __float2half((v0-mean)*rs*w[t]     + b[t]);
    o[t+256] = __float2half((v1-mean)*rs*w[t+256] + b[t+256]);
    o[t+512] = __float2half((v2-mean)*rs*w[t+512] + b[t+512]);
}

/* ------------------------------ FFT stages ------------------------------ */
/* F1: ln1(applied inline via stats) + rfft along w (16 -> 9) */
__global__ __launch_bounds__(256) void fft_fwd_w(const float* __restrict__ tt,
                                                 const float2* __restrict__ st,
                                                 const float* __restrict__ lw,
                                                 const float* __restrict__ lb,
                                                 float* __restrict__ fr,
                                                 float* __restrict__ fi) {
    __shared__ float ct[16], stab[16];
    int t = threadIdx.x;
    if (t < 16) { ct[t] = cospif(t * 0.125f); stab[t] = sinpif(t * 0.125f); }
    __syncthreads();
    int gid = blockIdx.x * 256 + t;
    int d = gid % DIM; int hb = gid / DIM; int h = hb & 15; int b = hb >> 4;
    int rowbase = b*256 + h*16;
    float wd = lw[d], bd = lb[d];
    float v[16];
    const float* src = tt + (size_t)rowbase * DIM + d;
    #pragma unroll
    for (int w = 0; w < 16; w++) {
        float2 s = __ldg(&st[rowbase + w]);
        v[w] = (src[(size_t)w * DIM] - s.x) * s.y * wd + bd;
    }
    size_t o = (size_t)(b*16 + h) * 9 * DIM + d;
    #pragma unroll
    for (int k = 0; k < 9; k++) {
        float sr = 0.f, si = 0.f;
        #pragma unroll
        for (int w = 0; w < 16; w++) {
            int m = (k * w) & 15;
            sr = fmaf(v[w],  ct[m], sr);
            si = fmaf(v[w], -stab[m], si);
        }
        fr[o + (size_t)k * DIM] = sr;
        fi[o + (size_t)k * DIM] = si;
    }
}

__global__ __launch_bounds__(256) void fft_h_mod(float* __restrict__ fr,
                                                 float* __restrict__ fi,
                                                 const float* __restrict__ cw) {
    __shared__ float ct[16], st[16];
    int t = threadIdx.x;
    if (t < 16) { ct[t] = cospif(t * 0.125f); st[t] = sinpif(t * 0.125f); }
    __syncthreads();
    int gid = blockIdx.x * 256 + t;
    int d = gid % DIM; int kb = gid / DIM; int k = kb % 9; int b = kb / 9;
    size_t base = ((size_t)b * 16 * 9 + k) * DIM + d;
    float gr[16], gi[16];
    #pragma unroll
    for (int h = 0; h < 16; h++) {
        gr[h] = fr[base + (size_t)h * 9 * DIM];
        gi[h] = fi[base + (size_t)h * 9 * DIM];
    }
    float Gr[16], Gi[16];
    #pragma unroll
    for (int u = 0; u < 16; u++) {
        float ar = 0.f, ai = 0.f;
        #pragma unroll
        for (int h = 0; h < 16; h++) {
            int m = (u * h) & 15; float c = ct[m], s = st[m];
            ar = fmaf(gr[h], c, fmaf(gi[h],  s, ar));
            ai = fmaf(gi[h], c, fmaf(gr[h], -s, ai));
        }
        const float* wp = cw + ((size_t)(u*9 + k) * DIM + d) * 2;
        float wr = wp[0], wi = wp[1];
        Gr[u] = ar * wr - ai * wi;
        Gi[u] = ar * wi + ai * wr;
    }
    #pragma unroll
    for (int h = 0; h < 16; h++) {
        float ar = 0.f, ai = 0.f;
        #pragma unroll
        for (int u = 0; u < 16; u++) {
            int m = (u * h) & 15; float c = ct[m], s = st[m];
            ar = fmaf(Gr[u], c, fmaf(Gi[u], -s, ar));
            ai = fmaf(Gr[u], s, fmaf(Gi[u],  c, ai));
        }
        fr[base + (size_t)h * 9 * DIM] = ar;
        fi[base + (size_t)h * 9 * DIM] = ai;
    }
}

__global__ __launch_bounds__(256) void fft_inv_w(const float* __restrict__ fr,
                                                 const float* __restrict__ fi,
                                                 float* __restrict__ y) {
    __shared__ float ct[16], st[16];
    int t = threadIdx.x;
    if (t < 16) { ct[t] = cospif(t * 0.125f); st[t] = sinpif(t * 0.125f); }
    __syncthreads();
    int gid = blockIdx.x * 256 + t;
    int d = gid % DIM; int hb = gid / DIM; int h = hb & 15; int b = hb >> 4;
    size_t base = (size_t)(b*16 + h) * 9 * DIM + d;
    float vr[9], vi[9];
    #pragma unroll
    for (int k = 0; k < 9; k++) {
        vr[k] = fr[base + (size_t)k * DIM];
        vi[k] = fi[base + (size_t)k * DIM];
    }
    float* dst = y + (size_t)(b*256 + h*16) * DIM + d;
    #pragma unroll
    for (int w = 0; w < 16; w++) {
        float s = vr[0] + ((w & 1) ? -vr[8] : vr[8]);
        #pragma unroll
        for (int k = 1; k < 8; k++) {
            int m = (k * w) & 15;
            s = fmaf(2.f * vr[k], ct[m], s);
            s = fmaf(-2.f * vi[k], st[m], s);
        }
        dst[(size_t)w * DIM] = s * (1.f / 256.f);
    }
}

/* ------------------------------ final LN + mean + head ------------------------------ */
__global__ __launch_bounds__(256) void head_k(const float* __restrict__ tt,
                                              const float* __restrict__ nw,
                                              const float* __restrict__ nb,
                                              const float* __restrict__ hw,
                                              const float* __restrict__ hb,
                                              float* __restrict__ out) {
    __shared__ float2 red[8];
    int b = blockIdx.x, t = threadIdx.x;
    float a0 = 0.f, a1 = 0.f, a2 = 0.f;
    for (int p = 0; p < 256; p++) {
        const float* r = tt + (size_t)(b*256 + p) * DIM;
        float v0 = r[t], v1 = r[t+256], v2 = r[t+512];
        float2 R = block_reduce2(v0+v1+v2, v0*v0+v1*v1+v2*v2, red);
        float mean = R.x * (1.f/768.f);
        float var  = R.y * (1.f/768.f) - mean*mean;
        float rs = rsqrtf(var + LN_EPS);
        a0 += (v0-mean)*rs; a1 += (v1-mean)*rs; a2 += (v2-mean)*rs;
    }
    float f0 = a0 * nw[t]     * (1.f/256.f) + nb[t];
    float f1 = a1 * nw[t+256] * (1.f/256.f) + nb[t+256];
    float f2 = a2 * nw[t+512] * (1.f/256.f) + nb[t+512];
    float p0 = f0*hw[t]       + f1*hw[t+256]     + f2*hw[t+512];
    float p1 = f0*hw[768+t]   + f1*hw[768+t+256] + f2*hw[768+t+512];
    float2 R = block_reduce2(p0, p1, red);
    if (t == 0) {
        out[b*2 + 0] = R.x + hb[0];
        out[b*2 + 1] = R.y + hb[1];
    }
}

/* ------------------------------ launch ------------------------------ */
extern "C" void kernel_launch(void* const* d_in, const int* in_sizes, int n_in,
                              void* d_out, int out_size) {
    const float* x      = (const float*)d_in[0];
    const float* conv_w = (const float*)d_in[1];
    const float* conv_b = (const float*)d_in[2];
    const float* pos    = (const float*)d_in[3];
    const float* cw     = (const float*)d_in[4];
    const float* ln1w   = (const float*)d_in[5];
    const float* ln1b   = (const float*)d_in[6];
    const float* ln2w   = (const float*)d_in[7];
    const float* ln2b   = (const float*)d_in[8];
    const float* fc1w   = (const float*)d_in[9];
    const float* fc1b   = (const float*)d_in[10];
    const float* fc2w   = (const float*)d_in[11];
    const float* fc2b   = (const float*)d_in[12];
    const float* normw  = (const float*)d_in[13];
    const float* normb  = (const float*)d_in[14];
    const float* headw  = (const float*)d_in[15];
    const float* headb  = (const float*)d_in[16];
    float* out = (float*)d_out;
    (void)in_sizes; (void)n_in; (void)out_size;

    float *pt, *py, *pfr, *pfi;
    float2* pst;
    __half *pxh, *pah, *phh, *pw1h, *pw2h, *pwch;
    cudaGetSymbolAddress((void**)&pt,   g_t);
    cudaGetSymbolAddress((void**)&py,   g_y);
    cudaGetSymbolAddress((void**)&pst,  g_st);
    cudaGetSymbolAddress((void**)&pfr,  g_fr);
    cudaGetSymbolAddress((void**)&pfi,  g_fi);
    cudaGetSymbolAddress((void**)&pxh,  g_xh);
    cudaGetSymbolAddress((void**)&pah,  g_ah);
    cudaGetSymbolAddress((void**)&phh,  g_hh);
    cudaGetSymbolAddress((void**)&pw1h, g_w1h);
    cudaGetSymbolAddress((void**)&pw2h, g_w2h);
    cudaGetSymbolAddress((void**)&pwch, g_wch);

    static bool attr_set = false;
    if (!attr_set) {
        cudaFuncSetAttribute(gemm_mma<0>, cudaFuncAttributeMaxDynamicSharedMemorySize, GSMEM);
        cudaFuncSetAttribute(gemm_mma<1>, cudaFuncAttributeMaxDynamicSharedMemorySize, GSMEM);
        cudaFuncSetAttribute(gemm_mma<2>, cudaFuncAttributeMaxDynamicSharedMemorySize, GSMEM);
        attr_set = true;
    }

    /* fp16 weights */
    round_h<<<(DIM*DIM + 255)/256, 256>>>(conv_w, pwch, DIM*DIM);
    round_h<<<(8*HID*DIM + 255)/256, 256>>>(fc1w, pw1h, 8*HID*DIM);
    round_h<<<(8*DIM*HID + 255)/256, 256>>>(fc2w, pw2h, 8*DIM*HID);

    /* patch embed */
    im2col_k<<<(MROWS * DIM) / 256, 256>>>(x, pxh);
    gemm_mma<0><<<dim3(DIM/128, MROWS/128), 256, GSMEM>>>(pxh, pwch, conv_b, pos, pt,
                                                          MROWS, DIM, DIM);

    const int nF1 = (BATCH * 16 * DIM) / 256;
    const int nF2 = (BATCH * 9  * DIM) / 256;

    for (int i = 0; i < 8; i++) {
        ln_stats_k<<<MROWS, 256>>>(pt, pst);
        fft_fwd_w<<<nF1, 256>>>(pt, pst, ln1w + i*DIM, ln1b + i*DIM, pfr, pfi);
        fft_h_mod<<<nF2, 256>>>(pfr, pfi, cw + (size_t)i * 16 * 9 * DIM * 2);
        fft_inv_w<<<nF1, 256>>>(pfr, pfi, py);
        ln_to_h<<<MROWS, 256>>>(py, pah, ln2w + i*DIM, ln2b + i*DIM);
        gemm_mma<1><<<dim3(HID/128, MROWS/128), 256, GSMEM>>>(
            pah, pw1h + (size_t)i*HID*DIM, fc1b + i*HID, nullptr, phh, MROWS, HID, DIM);
        gemm_mma<2><<<dim3(DIM/128, MROWS/128), 256, GSMEM>>>(
            phh, pw2h + (size_t)i*DIM*HID, fc2b + i*DIM, nullptr, pt, MROWS, DIM, HID);
    }

    head_k<<<BATCH, 256>>>(pt, normw, normb, headw, headb, out);
}